// round 12
// baseline (speedup 1.0000x reference)
#include <cuda_runtime.h>
#include <cuda_bf16.h>
#include <cstdint>
#include <cstddef>

#define NMAX 98304
#define EMAX 786432
#define BMAX 512

__device__ float g_h   [(size_t)NMAX * 128];
__device__ float g_eenc[(size_t)EMAX * 64];
__device__ float g_eP  [(size_t)EMAX * 128];
__device__ __nv_bfloat16 g_ABh [(size_t)NMAX * 1024];
__device__ __nv_bfloat16 g_eMc [(size_t)EMAX * 256];
__device__ __nv_bfloat16 g_eRc [(size_t)EMAX * 256];
__device__ __nv_bfloat16 g_W1cb[1024 * 128];
__device__ float g_aggH[(size_t)NMAX * 512];
__device__ float g_cat [(size_t)NMAX * 256];
__device__ float g_hid [(size_t)NMAX * 256];
__device__ float g_t   [(size_t)BMAX * 2 * 128 * 128];
__device__ float g_stk [(size_t)BMAX * 2 * 128 * 128];
__device__ float g_la  [(size_t)BMAX * 128 * 128];
__device__ float g_W2cat[512 * 128];
__device__ float g_Wecat[64 * 512];
__device__ float g_becat[512];
__device__ int   g_sizes [2 * BMAX];
__device__ int   g_starts[2 * BMAX + 1];
__device__ int   g_din [NMAX];
__device__ int   g_dout[NMAX];
__device__ int   g_pin [NMAX + 1];
__device__ int   g_pout[NMAX + 1];
__device__ int   g_cin [NMAX];
__device__ int   g_cout[NMAX];
__device__ int   g_iin [EMAX];
__device__ int   g_iout[EMAX];
__device__ int   g_oin [EMAX];
__device__ int   g_oout[EMAX];

__device__ __forceinline__ float warp_max(float v) {
    #pragma unroll
    for (int o = 16; o; o >>= 1) v = fmaxf(v, __shfl_xor_sync(0xffffffffu, v, o));
    return v;
}
__device__ __forceinline__ float warp_sum(float v) {
    #pragma unroll
    for (int o = 16; o; o >>= 1) v += __shfl_xor_sync(0xffffffffu, v, o);
    return v;
}
__device__ __forceinline__ uint32_t f2tf32(float x) {
    uint32_t r;
    asm("cvt.rna.tf32.f32 %0, %1;" : "=r"(r) : "f"(x));
    return r;
}
__device__ __forceinline__ uint32_t pkbf(float x, float y) {
    __nv_bfloat162 h = __floats2bfloat162_rn(x, y);
    return *(uint32_t*)&h;
}
__device__ __forceinline__ void mma_tf32(float* d, const uint32_t* a, const uint32_t* b) {
    asm volatile(
        "mma.sync.aligned.m16n8k8.row.col.f32.tf32.tf32.f32 "
        "{%0,%1,%2,%3}, {%4,%5,%6,%7}, {%8,%9}, {%0,%1,%2,%3};"
        : "+f"(d[0]), "+f"(d[1]), "+f"(d[2]), "+f"(d[3])
        : "r"(a[0]), "r"(a[1]), "r"(a[2]), "r"(a[3]), "r"(b[0]), "r"(b[1]));
}
__device__ __forceinline__ void mma_bf16(float* d, const uint32_t* a, const uint32_t* b) {
    asm volatile(
        "mma.sync.aligned.m16n8k16.row.col.f32.bf16.bf16.f32 "
        "{%0,%1,%2,%3}, {%4,%5,%6,%7}, {%8,%9}, {%0,%1,%2,%3};"
        : "+f"(d[0]), "+f"(d[1]), "+f"(d[2]), "+f"(d[3])
        : "r"(a[0]), "r"(a[1]), "r"(a[2]), "r"(a[3]), "r"(b[0]), "r"(b[1]));
}
__device__ __forceinline__ void store2(float v0, float v1, float* p) {
    p[0] = v0; p[1] = v1;
}
__device__ __forceinline__ void store2(float v0, float v1, __nv_bfloat16* p) {
    *(__nv_bfloat162*)p = __floats2bfloat162_rn(v0, v1);
}

__global__ void zero_f(float* p, size_t n) {
    for (size_t i = (size_t)blockIdx.x * 256 + threadIdx.x; i < n;
         i += (size_t)gridDim.x * 256) p[i] = 0.f;
}
__global__ void zero_i(int* p, int n) {
    int i = blockIdx.x * 256 + threadIdx.x;
    if (i < n) p[i] = 0;
}
__global__ void copy_i(const int* a, int* b, int n) {
    int i = blockIdx.x * 256 + threadIdx.x;
    if (i < n) b[i] = a[i];
}

// ---------------------------------------------------------------------------
// Fused ABp GEMM: ABh[tile] = bf16( h_tile(128x128) @ W1cb^T(128x1024) ).
// A converted to bf16 ONCE into smem (fragment layout); loop over 8 N-blocks
// of B (bf16, L2-resident). 8 warps = 4M x 2N, warp tile 32x64, 64 acc regs.
// Kills the 8x redundant A-read traffic of the blocked variant.
// smem: A 8*128*5 uint2 (40KB) + B same (40KB).
// ---------------------------------------------------------------------------
__global__ __launch_bounds__(256, 2) void abp_fused(
    const float* __restrict__ h, const __nv_bfloat16* __restrict__ W1cb,
    __nv_bfloat16* __restrict__ ABh)
{
    extern __shared__ uint2 sm[];          // [0:5120) A, [5120:10240) B
    uint2* As = sm;                        // As[kc*640 + m*5 + c]
    uint2* Bs = sm + 5120;                 // Bs[kc*640 + n*5 + c]
    const int t = threadIdx.x, lane = t & 31, warp = t >> 5;
    const int row0 = blockIdx.x * 128;
    const int g = lane >> 2, c = lane & 3;
    const int wm = (warp & 3) * 32;
    const int wn = (warp >> 2) * 64;
    const int lr = t >> 1, ah = t & 1;     // loader: row lr, k-half ah

    // ---- A tile: fp32 -> bf16 fragment layout, once ----
    {
        const float* hp = h + (size_t)(row0 + lr) * 128 + 64 * ah;
        #pragma unroll
        for (int kq = 0; kq < 4; ++kq) {   // kc = 4*ah + kq
            float f[16];
            #pragma unroll
            for (int j = 0; j < 4; ++j) *(float4*)(f + 4 * j) = *(const float4*)(hp + 16 * kq + 4 * j);
            int kc = 4 * ah + kq;
            #pragma unroll
            for (int cc = 0; cc < 4; ++cc)
                As[kc * 640 + lr * 5 + cc] =
                    make_uint2(pkbf(f[2 * cc], f[2 * cc + 1]), pkbf(f[2 * cc + 8], f[2 * cc + 9]));
        }
    }

    for (int nc = 0; nc < 8; ++nc) {
        __syncthreads();
        // ---- B block: rows nc*128..+128 of W1cb, bf16 -> fragment layout ----
        {
            const uint32_t* wp = (const uint32_t*)(W1cb + (size_t)(nc * 128 + lr) * 128) + 32 * ah;
            uint32_t r[32];
            #pragma unroll
            for (int j = 0; j < 8; ++j) *(uint4*)(r + 4 * j) = *(const uint4*)(wp + 4 * j);
            #pragma unroll
            for (int kq = 0; kq < 4; ++kq) {
                int kc = 4 * ah + kq;
                #pragma unroll
                for (int cc = 0; cc < 4; ++cc)
                    Bs[kc * 640 + lr * 5 + cc] = make_uint2(r[8 * kq + cc], r[8 * kq + cc + 4]);
            }
        }
        __syncthreads();

        float acc[2][8][4];
        #pragma unroll
        for (int mi = 0; mi < 2; ++mi)
            #pragma unroll
            for (int ni = 0; ni < 8; ++ni)
                #pragma unroll
                for (int j = 0; j < 4; ++j) acc[mi][ni][j] = 0.f;

        #pragma unroll
        for (int kc = 0; kc < 8; ++kc) {
            uint32_t af[2][4];
            #pragma unroll
            for (int mi = 0; mi < 2; ++mi) {
                int m = wm + mi * 16;
                uint2 u0 = As[kc * 640 + (m + g) * 5 + c];
                uint2 u1 = As[kc * 640 + (m + g + 8) * 5 + c];
                af[mi][0] = u0.x; af[mi][1] = u1.x;
                af[mi][2] = u0.y; af[mi][3] = u1.y;
            }
            uint32_t bf[8][2];
            #pragma unroll
            for (int ni = 0; ni < 8; ++ni) {
                uint2 v = Bs[kc * 640 + (wn + ni * 8 + g) * 5 + c];
                bf[ni][0] = v.x; bf[ni][1] = v.y;
            }
            #pragma unroll
            for (int mi = 0; mi < 2; ++mi)
                #pragma unroll
                for (int ni = 0; ni < 8; ++ni)
                    mma_bf16(acc[mi][ni], af[mi], bf[ni]);
        }

        // ---- epilogue: write this 128x128 block of ABh as bf16 ----
        #pragma unroll
        for (int mi = 0; mi < 2; ++mi) {
            #pragma unroll
            for (int ni = 0; ni < 8; ++ni) {
                int col = nc * 128 + wn + ni * 8 + 2 * c;
                #pragma unroll
                for (int half = 0; half < 2; ++half) {
                    int row = row0 + wm + mi * 16 + g + half * 8;
                    *(__nv_bfloat162*)(ABh + (size_t)row * 1024 + col) =
                        __floats2bfloat162_rn(acc[mi][ni][2 * half], acc[mi][ni][2 * half + 1]);
                }
            }
        }
    }
}

// ---------------------------------------------------------------------------
// tf32 tensor-core GEMM, double-buffered smem pipeline.
// ---------------------------------------------------------------------------
template <int BN, int EPI, typename OutT>
__global__ __launch_bounds__(256) void gemm_tf32(
    const float* __restrict__ A, int lda, const float* __restrict__ W, int ldb,
    OutT* __restrict__ C, int ldc, const float* __restrict__ bias, int K)
{
    constexpr int BM = 128, BK = 16;
    constexpr int WN = BN / 4;
    constexpr int NI = WN / 8;
    constexpr int NITB = (BK * BN) / 1024;
    __shared__ uint2    As2[2][2][BM][4];
    __shared__ uint32_t Bs[2][BK][BN + 8];
    const int row0 = blockIdx.y * BM, col0 = blockIdx.x * BN;
    const int t = threadIdx.x, lane = t & 31, warp = t >> 5;
    const int wm = (warp & 1) * 64;
    const int wn = (warp >> 1) * WN;
    const int g = lane >> 2, c = lane & 3;
    const int am = t >> 1, aks = t & 1;

    float acc[4][NI][4];
    #pragma unroll
    for (int mi = 0; mi < 4; ++mi)
        #pragma unroll
        for (int ni = 0; ni < NI; ++ni)
            #pragma unroll
            for (int j = 0; j < 4; ++j) acc[mi][ni][j] = 0.f;

    float4 ra0, ra1, rb[NITB];

    auto gload = [&](int k0) {
        const float* ap = &A[(size_t)(row0 + am) * lda + k0 + aks * 8];
        ra0 = *(const float4*)(ap);
        ra1 = *(const float4*)(ap + 4);
        #pragma unroll
        for (int it = 0; it < NITB; ++it) {
            int kk = t / (BN / 4) + it * (1024 / BN);
            int nq = (t % (BN / 4)) * 4;
            rb[it] = *(const float4*)&W[(size_t)(k0 + kk) * ldb + col0 + nq];
        }
    };
    auto sstore = [&](int p) {
        As2[p][aks][am][0] = make_uint2(f2tf32(ra0.x), f2tf32(ra1.x));
        As2[p][aks][am][1] = make_uint2(f2tf32(ra0.y), f2tf32(ra1.y));
        As2[p][aks][am][2] = make_uint2(f2tf32(ra0.z), f2tf32(ra1.z));
        As2[p][aks][am][3] = make_uint2(f2tf32(ra0.w), f2tf32(ra1.w));
        #pragma unroll
        for (int it = 0; it < NITB; ++it) {
            int kk = t / (BN / 4) + it * (1024 / BN);
            int nq = (t % (BN / 4)) * 4;
            uint32_t* dst = &Bs[p][kk][nq];
            dst[0] = f2tf32(rb[it].x); dst[1] = f2tf32(rb[it].y);
            dst[2] = f2tf32(rb[it].z); dst[3] = f2tf32(rb[it].w);
        }
    };
    auto scompute = [&](int p) {
        #pragma unroll
        for (int ks = 0; ks < 2; ++ks) {
            const int kb = ks * 8;
            uint32_t af[4][4];
            #pragma unroll
            for (int mi = 0; mi < 4; ++mi) {
                int m = wm + mi * 16;
                uint2 u0 = As2[p][ks][m + g][c];
                uint2 u1 = As2[p][ks][m + g + 8][c];
                af[mi][0] = u0.x; af[mi][1] = u1.x;
                af[mi][2] = u0.y; af[mi][3] = u1.y;
            }
            uint32_t bf[NI][2];
            #pragma unroll
            for (int ni = 0; ni < NI; ++ni) {
                int n = wn + ni * 8 + g;
                bf[ni][0] = Bs[p][kb + c][n];
                bf[ni][1] = Bs[p][kb + c + 4][n];
            }
            #pragma unroll
            for (int mi = 0; mi < 4; ++mi)
                #pragma unroll
                for (int ni = 0; ni < NI; ++ni)
                    mma_tf32(acc[mi][ni], af[mi], bf[ni]);
        }
    };

    gload(0);
    sstore(0);
    __syncthreads();
    int p = 0;
    for (int k0 = 0; k0 < K; k0 += BK) {
        const bool more = (k0 + BK < K);
        if (more) gload(k0 + BK);
        scompute(p);
        if (more) sstore(p ^ 1);
        __syncthreads();
        p ^= 1;
    }
    #pragma unroll
    for (int mi = 0; mi < 4; ++mi) {
        #pragma unroll
        for (int ni = 0; ni < NI; ++ni) {
            int row = row0 + wm + mi * 16 + g;
            int col = col0 + wn + ni * 8 + 2 * c;
            #pragma unroll
            for (int half = 0; half < 2; ++half) {
                int r = row + half * 8;
                float v0 = acc[mi][ni][2 * half + 0];
                float v1 = acc[mi][ni][2 * half + 1];
                if (EPI >= 1) { v0 += bias[col]; v1 += bias[col + 1]; }
                if (EPI == 2) { v0 = fmaxf(v0, 0.f); v1 = fmaxf(v1, 0.f); }
                size_t off = (size_t)r * ldc + col;
                if (EPI == 3) { C[off] += v0; C[off + 1] += v1; }
                else          store2(v0, v1, &C[off]);
            }
        }
    }
}

__global__ void pack_w1cb(const float* __restrict__ m1, const float* __restrict__ r1,
                          __nv_bfloat16* __restrict__ w) {
    int i = blockIdx.x * 256 + threadIdx.x;
    if (i >= 1024 * 128) return;
    int n = i >> 7, k = i & 127;
    float v;
    if (n < 256)      v = m1[k * 256 + n];
    else if (n < 512) v = m1[(128 + k) * 256 + (n - 256)];
    else if (n < 768) v = r1[k * 256 + (n - 512)];
    else              v = r1[(128 + k) * 256 + (n - 768)];
    w[i] = __float2bfloat16(v);
}
__global__ void pack_w2cat(const float* __restrict__ m2, const float* __restrict__ r2,
                           float* __restrict__ w) {
    int i = blockIdx.x * 256 + threadIdx.x;
    if (i >= 512 * 128) return;
    int k = i >> 7, j = i & 127;
    w[i] = (k < 256) ? m2[k * 128 + j] : r2[(k - 256) * 128 + j];
}
__global__ void pack_wecat(const float* __restrict__ m1, const float* __restrict__ r1,
                           const float* __restrict__ mb1, const float* __restrict__ rb1,
                           float* __restrict__ w, float* __restrict__ bcat) {
    int i = blockIdx.x * 256 + threadIdx.x;
    if (i < 64 * 512) {
        int k = i >> 9, j = i & 511;
        w[i] = (j < 256) ? m1[(256 + k) * 256 + j] : r1[(256 + k) * 256 + (j - 256)];
    }
    if (i < 512) bcat[i] = (i < 256) ? mb1[i] : rb1[i - 256];
}

__global__ void deg_count(const int* __restrict__ fr, const int* __restrict__ to,
                          int* din, int* dout, int E) {
    int e = blockIdx.x * 256 + threadIdx.x;
    if (e < E) { atomicAdd(&din[to[e]], 1); atomicAdd(&dout[fr[e]], 1); }
}
__global__ void exscan_kernel(const int* __restrict__ in, int* __restrict__ out, int n) {
    __shared__ int buf[1024];
    __shared__ int carry_s;
    int t = threadIdx.x;
    if (t == 0) carry_s = 0;
    __syncthreads();
    for (int base = 0; base < n; base += 1024) {
        int i = base + t;
        int v = (i < n) ? in[i] : 0;
        buf[t] = v;
        __syncthreads();
        for (int d = 1; d < 1024; d <<= 1) {
            int x = (t >= d) ? buf[t - d] : 0;
            __syncthreads();
            buf[t] += x;
            __syncthreads();
        }
        if (i < n) out[i] = carry_s + buf[t] - v;
        int tot = buf[1023];
        __syncthreads();
        if (t == 0) carry_s += tot;
        __syncthreads();
    }
    if (t == 0) out[n] = carry_s;
}
__global__ void csr_fill(const int* __restrict__ fr, const int* __restrict__ to,
                         int* cin, int* cout, int* iin, int* iout, int E) {
    int e = blockIdx.x * 256 + threadIdx.x;
    if (e < E) {
        int s  = atomicAdd(&cin [to[e]], 1); iin [s]  = e;
        int s2 = atomicAdd(&cout[fr[e]], 1); iout[s2] = e;
    }
}

__global__ __launch_bounds__(256) void permute_eenc(
    const float* __restrict__ eenc, const int* __restrict__ idx,
    const int* __restrict__ endp, float* __restrict__ out,
    int* __restrict__ ocsr, int E)
{
    int j = blockIdx.x * 8 + (threadIdx.x >> 5);
    if (j >= E) return;
    int lane = threadIdx.x & 31;
    int e = idx[j];
    if (lane == 0) ocsr[j] = endp[e];
    const float2* s2 = (const float2*)(eenc + (size_t)e * 64);
    float2* d2 = (float2*)(out + (size_t)j * 64);
    d2[lane] = s2[lane];
}

__global__ __launch_bounds__(256) void agg_kernel(
    const int* __restrict__ ptr, const int* __restrict__ ocsr,
    const __nv_bfloat162* __restrict__ AB, int aoff, int boff,
    const __nv_bfloat162* __restrict__ ecsr,
    float* __restrict__ aggH, int ooff, int Nn)
{
    int n = (blockIdx.x * blockDim.x + threadIdx.x) >> 5;
    int lane = threadIdx.x & 31;
    if (n >= Nn) return;
    float bv[8], acc[8];
    const __nv_bfloat162* bp = AB + (size_t)n * 512 + boff;
    #pragma unroll
    for (int k = 0; k < 4; ++k) {
        float2 b2 = __bfloat1622float2(bp[lane + 32 * k]);
        bv[2 * k] = b2.x; bv[2 * k + 1] = b2.y;
        acc[2 * k] = 0.f; acc[2 * k + 1] = 0.f;
    }
    int s = ptr[n], e1 = ptr[n + 1];
    for (int j = s; j < e1; ++j) {
        int o = ocsr[j];
        const __nv_bfloat162* ap = AB + (size_t)o * 512 + aoff;
        const __nv_bfloat162* ep = ecsr + (size_t)j * 128;
        #pragma unroll
        for (int k = 0; k < 4; ++k) {
            float2 a2 = __bfloat1622float2(ap[lane + 32 * k]);
            float2 e2 = __bfloat1622float2(ep[lane + 32 * k]);
            acc[2 * k]     += fmaxf(a2.x + e2.x + bv[2 * k],     0.f);
            acc[2 * k + 1] += fmaxf(a2.y + e2.y + bv[2 * k + 1], 0.f);
        }
    }
    float2* op = (float2*)(aggH + (size_t)n * 512 + ooff);
    #pragma unroll
    for (int k = 0; k < 4; ++k) op[lane + 32 * k] = make_float2(acc[2 * k], acc[2 * k + 1]);
}

__global__ void biascat_kernel(float* __restrict__ cat, const float* __restrict__ h,
                               const int* __restrict__ pin, const int* __restrict__ pout,
                               const float* __restrict__ mb2, const float* __restrict__ rb2) {
    int n = blockIdx.x, t = threadIdx.x;
    if (t < 128) {
        float di = (float)(pin [n + 1] - pin [n]);
        float dz = (float)(pout[n + 1] - pout[n]);
        cat[(size_t)n * 256 + t] += di * mb2[t] + dz * rb2[t];
    } else {
        cat[(size_t)n * 256 + t] = h[(size_t)n * 128 + (t - 128)];
    }
}

__global__ void build_sizes(const int* __restrict__ qs, const int* __restrict__ cs,
                            int* __restrict__ sizes, int B2) {
    int i = blockIdx.x * 256 + threadIdx.x;
    if (i < B2) sizes[i] = (i & 1) ? cs[i >> 1] : qs[i >> 1];
}
__global__ void scatter_kernel(const float* __restrict__ h, const int* __restrict__ gidx,
                               const int* __restrict__ starts, float* __restrict__ st) {
    int n = blockIdx.x, t = threadIdx.x;
    int g = gidx[n];
    int pos = n - starts[g];
    st[((size_t)g * 128 + pos) * 128 + t] = h[(size_t)n * 128 + t];
}
__global__ void mask_kernel(float* __restrict__ tt, const int* __restrict__ qs,
                            const int* __restrict__ cs) {
    int r = blockIdx.x, j = threadIdx.x;
    int b = r >> 8, side = (r >> 7) & 1, pos = r & 127;
    int sz = side ? cs[b] : qs[b];
    if (pos >= sz) tt[(size_t)r * 128 + j] = 0.f;
}

__global__ __launch_bounds__(256) void pair_gemm_kernel(const float* __restrict__ tt,
                                                        float* __restrict__ la) {
    int b = blockIdx.x;
    const float* Aq = tt + (size_t)(2 * b)     * 16384;
    const float* Ac = tt + (size_t)(2 * b + 1) * 16384;
    __shared__ float As[16][132], Bs[16][132];
    int t = threadIdx.x, tx = t & 15, ty = t >> 4;
    float acc[8][8];
    #pragma unroll
    for (int i = 0; i < 8; ++i)
        #pragma unroll
        for (int j = 0; j < 8; ++j) acc[i][j] = 0.f;
    for (int k0 = 0; k0 < 128; k0 += 16) {
        #pragma unroll
        for (int it = 0; it < 2; ++it) {
            int m = (t >> 2) + it * 64, kq = (t & 3) * 4;
            float4 v = *(const float4*)&Aq[m * 128 + k0 + kq];
            As[kq][m] = v.x; As[kq + 1][m] = v.y; As[kq + 2][m] = v.z; As[kq + 3][m] = v.w;
            float4 w = *(const float4*)&Ac[m * 128 + k0 + kq];
            Bs[kq][m] = w.x; Bs[kq + 1][m] = w.y; Bs[kq + 2][m] = w.z; Bs[kq + 3][m] = w.w;
        }
        __syncthreads();
        #pragma unroll
        for (int k = 0; k < 16; ++k) {
            float a[8], bv[8];
            *(float4*)(a)      = *(const float4*)&As[k][ty * 8];
            *(float4*)(a + 4)  = *(const float4*)&As[k][ty * 8 + 4];
            *(float4*)(bv)     = *(const float4*)&Bs[k][tx * 8];
            *(float4*)(bv + 4) = *(const float4*)&Bs[k][tx * 8 + 4];
            #pragma unroll
            for (int i = 0; i < 8; ++i)
                #pragma unroll
                for (int j = 0; j < 8; ++j) acc[i][j] += a[i] * bv[j];
        }
        __syncthreads();
    }
    float* dst = la + (size_t)b * 16384;
    #pragma unroll
    for (int i = 0; i < 8; ++i)
        #pragma unroll
        for (int j = 0; j < 8; ++j)
            dst[(ty * 8 + i) * 128 + tx * 8 + j] = acc[i][j] * 10.0f;
}

__global__ __launch_bounds__(256) void sinkhorn_kernel(float* __restrict__ la_g,
                                                       const int* __restrict__ qs,
                                                       const int* __restrict__ cs) {
    extern __shared__ float P[];
    const int b = blockIdx.x;
    const int R = qs[b], C = cs[b];
    const float wR = (float)(128 - R), wC = (float)(128 - C);
    const int RT = (R < 128) ? R + 1 : 128;
    const int CT = (C < 128) ? C + 1 : 128;
    float* src = la_g + (size_t)b * 16384;
    const int t = threadIdx.x;
    for (int i = t; i < RT * CT; i += 256) {
        int q = i / CT, c = i % CT;
        P[q * 131 + c] = (q < R && c < C) ? src[q * 128 + c] : 0.f;
    }
    __syncthreads();
    const int warp = t >> 5, lane = t & 31;
    for (int iter = 0; iter < 20; ++iter) {
        for (int q = warp; q < RT; q += 8) {
            float m = -1e30f;
            for (int c = lane; c < CT; c += 32) m = fmaxf(m, P[q * 131 + c]);
            m = warp_max(m);
            float s = 0.f;
            for (int c = lane; c < CT; c += 32) {
                float w = (c == C) ? wC : 1.f;
                s += w * __expf(P[q * 131 + c] - m);
            }
            s = warp_sum(s);
            float lse = m + __logf(s);
            for (int c = lane; c < CT; c += 32) P[q * 131 + c] -= lse;
        }
        __syncthreads();
        for (int c = warp; c < CT; c += 8) {
            float m = -1e30f;
            for (int q = lane; q < RT; q += 32) m = fmaxf(m, P[q * 131 + c]);
            m = warp_max(m);
            float s = 0.f;
            for (int q = lane; q < RT; q += 32) {
                float w = (q == R) ? wR : 1.f;
                s += w * __expf(P[q * 131 + c] - m);
            }
            s = warp_sum(s);
            float lse = m + __logf(s);
            for (int q = lane; q < RT; q += 32) P[q * 131 + c] -= lse;
        }
        __syncthreads();
    }
    for (int i = t; i < 16384; i += 256) {
        int q = i >> 7, c = i & 127;
        int qe = (q < R) ? q : R;
        int ce = (c < C) ? c : C;
        src[i] = __expf(P[qe * 131 + ce]);
    }
}

__global__ __launch_bounds__(256) void score_kernel(const float* __restrict__ plan,
                                                    const float* __restrict__ stacked,
                                                    float* __restrict__ out) {
    int b = blockIdx.x;
    const float* P  = plan    + (size_t)b * 16384;
    const float* Q  = stacked + (size_t)(2 * b)     * 16384;
    const float* Cm = stacked + (size_t)(2 * b + 1) * 16384;
    __shared__ float As[16][132], Bs[16][132];
    int t = threadIdx.x, tx = t & 15, ty = t >> 4;
    float acc[8][8];
    #pragma unroll
    for (int i = 0; i < 8; ++i)
        #pragma unroll
        for (int j = 0; j < 8; ++j) acc[i][j] = 0.f;
    for (int k0 = 0; k0 < 128; k0 += 16) {
        #pragma unroll
        for (int it = 0; it < 2; ++it) {
            int m = (t >> 2) + it * 64, kq = (t & 3) * 4;
            float4 v = *(const float4*)&P[m * 128 + k0 + kq];
            As[kq][m] = v.x; As[kq + 1][m] = v.y; As[kq + 2][m] = v.z; As[kq + 3][m] = v.w;
        }
        #pragma unroll
        for (int it = 0; it < 2; ++it) {
            int kk = (t >> 5) + it * 8, nq = (t & 31) * 4;
            *(float4*)&Bs[kk][nq] = *(const float4*)&Cm[(k0 + kk) * 128 + nq];
        }
        __syncthreads();
        #pragma unroll
        for (int k = 0; k < 16; ++k) {
            float a[8], bv[8];
            *(float4*)(a)      = *(const float4*)&As[k][ty * 8];
            *(float4*)(a + 4)  = *(const float4*)&As[k][ty * 8 + 4];
            *(float4*)(bv)     = *(const float4*)&Bs[k][tx * 8];
            *(float4*)(bv + 4) = *(const float4*)&Bs[k][tx * 8 + 4];
            #pragma unroll
            for (int i = 0; i < 8; ++i)
                #pragma unroll
                for (int j = 0; j < 8; ++j) acc[i][j] += a[i] * bv[j];
        }
        __syncthreads();
    }
    float s = 0.f;
    #pragma unroll
    for (int i = 0; i < 8; ++i)
        #pragma unroll
        for (int j = 0; j < 8; ++j)
            s += fmaxf(Q[(ty * 8 + i) * 128 + tx * 8 + j] - acc[i][j], 0.f);
    s = warp_sum(s);
    __shared__ float red[8];
    if ((t & 31) == 0) red[t >> 5] = s;
    __syncthreads();
    if (t == 0) {
        float tot = 0.f;
        #pragma unroll
        for (int i = 0; i < 8; ++i) tot += red[i];
        out[b] = -tot;
    }
}

template <typename T>
static T* sym(const void* s) { void* p = nullptr; cudaGetSymbolAddress(&p, s); return (T*)p; }

extern "C" void kernel_launch(void* const* d_in, const int* in_sizes, int n_in,
                              void* d_out, int out_size) {
    const float* nf  = (const float*)d_in[0];
    const float* ef  = (const float*)d_in[1];
    const float* enW = (const float*)d_in[2];  const float* enB = (const float*)d_in[3];
    const float* eeW = (const float*)d_in[4];  const float* eeB = (const float*)d_in[5];
    const float* m1  = (const float*)d_in[6];  const float* mb1 = (const float*)d_in[7];
    const float* m2  = (const float*)d_in[8];  const float* mb2 = (const float*)d_in[9];
    const float* r1  = (const float*)d_in[10]; const float* rb1 = (const float*)d_in[11];
    const float* r2  = (const float*)d_in[12]; const float* rb2 = (const float*)d_in[13];
    const float* u1  = (const float*)d_in[14]; const float* ub1 = (const float*)d_in[15];
    const float* u2  = (const float*)d_in[16]; const float* ub2 = (const float*)d_in[17];
    const float* f1  = (const float*)d_in[18]; const float* f1b = (const float*)d_in[19];
    const float* f2  = (const float*)d_in[20]; const float* f2b = (const float*)d_in[21];
    const int* fr  = (const int*)d_in[22];
    const int* to  = (const int*)d_in[23];
    const int* gix = (const int*)d_in[24];
    const int* qs  = (const int*)d_in[25];
    const int* cs  = (const int*)d_in[26];
    const int E  = in_sizes[22];
    const int N  = in_sizes[24];
    const int B  = in_sizes[25];
    const int B2 = 2 * B;
    float* out = (float*)d_out;

    float* h    = sym<float>(g_h);    float* eenc = sym<float>(g_eenc);
    float* eP   = sym<float>(g_eP);
    __nv_bfloat16* ABh = sym<__nv_bfloat16>(g_ABh);
    __nv_bfloat16* eMc = sym<__nv_bfloat16>(g_eMc);
    __nv_bfloat16* eRc = sym<__nv_bfloat16>(g_eRc);
    __nv_bfloat16* W1cb = sym<__nv_bfloat16>(g_W1cb);
    float* aggH = sym<float>(g_aggH); float* cat  = sym<float>(g_cat);
    float* hid  = sym<float>(g_hid);  float* tt   = sym<float>(g_t);
    float* stk  = sym<float>(g_stk);  float* la   = sym<float>(g_la);
    float* W2c = sym<float>(g_W2cat);
    float* Wec  = sym<float>(g_Wecat); float* bec = sym<float>(g_becat);
    int* sizes = sym<int>(g_sizes); int* starts = sym<int>(g_starts);
    int* din = sym<int>(g_din);   int* dout = sym<int>(g_dout);
    int* pin = sym<int>(g_pin);   int* pout = sym<int>(g_pout);
    int* cin = sym<int>(g_cin);   int* cout = sym<int>(g_cout);
    int* iin = sym<int>(g_iin);   int* iout = sym<int>(g_iout);
    int* oin = sym<int>(g_oin);   int* oout = sym<int>(g_oout);
    float* ePa = eP;
    float* ePb = eP + (size_t)EMAX * 64;

    const int ABP_SMEM = 2 * 5120 * 8;  // 80 KB

    static bool attr_set = false;
    if (!attr_set) {
        cudaFuncSetAttribute(sinkhorn_kernel,
                             cudaFuncAttributeMaxDynamicSharedMemorySize, 129 * 131 * 4);
        cudaFuncSetAttribute(abp_fused,
                             cudaFuncAttributeMaxDynamicSharedMemorySize, ABP_SMEM);
        attr_set = true;
    }

    // ---- launches 1-6; #4 (= ncu capture) is abp_fused ----
    gemm_tf32<128, 1, float><<<dim3(1, N / 128), 256>>>(nf, 32, enW, 128, h, 128, enB, 32);
    pack_w1cb<<<(1024 * 128 + 255) / 256, 256>>>(m1, r1, W1cb);
    pack_wecat<<<(64 * 512 + 255) / 256, 256>>>(m1, r1, mb1, rb1, Wec, bec);
    abp_fused<<<N / 128, 256, ABP_SMEM>>>(h, W1cb, ABh);
    pack_w2cat<<<(512 * 128 + 255) / 256, 256>>>(m2, r2, W2c);
    gemm_tf32<64, 1, float><<<dim3(1, E / 128), 256>>>(ef, 16, eeW, 64, eenc, 64, eeB, 16);

    // ---- graph structure ----
    zero_i<<<(N + 255) / 256, 256>>>(din, N);
    zero_i<<<(N + 255) / 256, 256>>>(dout, N);
    build_sizes<<<(B2 + 255) / 256, 256>>>(qs, cs, sizes, B2);
    exscan_kernel<<<1, 1024>>>(sizes, starts, B2);
    deg_count<<<(E + 255) / 256, 256>>>(fr, to, din, dout, E);
    exscan_kernel<<<1, 1024>>>(din, pin, N);
    exscan_kernel<<<1, 1024>>>(dout, pout, N);
    copy_i<<<(N + 255) / 256, 256>>>(pin, cin, N);
    copy_i<<<(N + 255) / 256, 256>>>(pout, cout, N);
    csr_fill<<<(E + 255) / 256, 256>>>(fr, to, cin, cout, iin, iout, E);

    // ---- edge constants: permute eenc, GEMM directly to bf16 CSR ----
    permute_eenc<<<(E + 7) / 8, 256>>>(eenc, iin,  fr, ePa, oin,  E);
    permute_eenc<<<(E + 7) / 8, 256>>>(eenc, iout, to, ePb, oout, E);
    gemm_tf32<128, 1, __nv_bfloat16><<<dim3(2, E / 128), 256>>>(
        ePa, 64, Wec, 512, eMc, 256, bec, 64);
    gemm_tf32<128, 1, __nv_bfloat16><<<dim3(2, E / 128), 256>>>(
        ePb, 64, Wec + 256, 512, eRc, 256, bec + 256, 64);

    // ---- propagation rounds (round 0's ABp already done above) ----
    for (int r = 0; r < 5; ++r) {
        if (r > 0)
            abp_fused<<<N / 128, 256, ABP_SMEM>>>(h, W1cb, ABh);
        agg_kernel<<<(N + 7) / 8, 256>>>(pin,  oin,  (const __nv_bfloat162*)ABh, 0,   128,
                                         (const __nv_bfloat162*)eMc, aggH, 0,   N);
        agg_kernel<<<(N + 7) / 8, 256>>>(pout, oout, (const __nv_bfloat162*)ABh, 256, 384,
                                         (const __nv_bfloat162*)eRc, aggH, 256, N);
        gemm_tf32<128, 0, float><<<dim3(1, N / 128), 256>>>(aggH, 512, W2c, 128, cat, 256, nullptr, 512);
        biascat_kernel<<<N, 256>>>(cat, h, pin, pout, mb2, rb2);
        gemm_tf32<128, 2, float><<<dim3(2, N / 128), 256>>>(cat, 256, u1, 256, hid, 256, ub1, 256);
        gemm_tf32<128, 3, float><<<dim3(1, N / 128), 256>>>(hid, 256, u2, 128, h, 128, ub2, 256);
    }

    // ---- stack + transform ----
    zero_f<<<2048, 256>>>(stk, (size_t)B2 * 16384);
    scatter_kernel<<<N, 128>>>(h, gix, starts, stk);
    gemm_tf32<128, 2, float><<<dim3(1, B2 * 128 / 128), 256>>>(stk, 128, f1, 128, hid, 128, f1b, 128);
    gemm_tf32<128, 1, float><<<dim3(1, B2 * 128 / 128), 256>>>(hid, 128, f2, 128, tt, 128, f2b, 128);
    mask_kernel<<<B2 * 128, 128>>>(tt, qs, cs);

    // ---- sinkhorn + score ----
    pair_gemm_kernel<<<B, 256>>>(tt, la);
    sinkhorn_kernel<<<B, 256, 129 * 131 * 4>>>(la, qs, cs);
    score_kernel<<<B, 256>>>(la, stk, out);
}

// round 13
// speedup vs baseline: 1.0141x; 1.0141x over previous
#include <cuda_runtime.h>
#include <cuda_bf16.h>
#include <cstdint>
#include <cstddef>

#define NMAX 98304
#define EMAX 786432
#define BMAX 512

__device__ float g_h   [(size_t)NMAX * 128];
__device__ float g_eenc[(size_t)EMAX * 64];
__device__ float g_eP  [(size_t)EMAX * 128];
__device__ __nv_bfloat16 g_ABh [(size_t)NMAX * 1024];
__device__ __nv_bfloat16 g_eMc [(size_t)EMAX * 256];
__device__ __nv_bfloat16 g_eRc [(size_t)EMAX * 256];
__device__ __nv_bfloat16 g_W1cb[1024 * 128];
__device__ float g_catA[(size_t)NMAX * 640];   // [aggM(256)|aggR(256)|h(128)]
__device__ float g_hid [(size_t)NMAX * 256];
__device__ float g_t   [(size_t)BMAX * 2 * 128 * 128];
__device__ float g_stk [(size_t)BMAX * 2 * 128 * 128];
__device__ float g_la  [(size_t)BMAX * 128 * 128];
__device__ float g_W2cat[512 * 128];
__device__ float g_W1u [640 * 256];            // [W21(512x256) ; u1_bot(128x256)]
__device__ float g_vm  [256];
__device__ float g_vr  [256];
__device__ float g_Wecat[64 * 512];
__device__ float g_becat[512];
__device__ int   g_sizes [2 * BMAX];
__device__ int   g_starts[2 * BMAX + 1];
__device__ int   g_din [NMAX];
__device__ int   g_dout[NMAX];
__device__ int   g_pin [NMAX + 1];
__device__ int   g_pout[NMAX + 1];
__device__ int   g_cin [NMAX];
__device__ int   g_cout[NMAX];
__device__ int   g_iin [EMAX];
__device__ int   g_iout[EMAX];
__device__ int   g_oin [EMAX];
__device__ int   g_oout[EMAX];

__device__ __forceinline__ float warp_max(float v) {
    #pragma unroll
    for (int o = 16; o; o >>= 1) v = fmaxf(v, __shfl_xor_sync(0xffffffffu, v, o));
    return v;
}
__device__ __forceinline__ float warp_sum(float v) {
    #pragma unroll
    for (int o = 16; o; o >>= 1) v += __shfl_xor_sync(0xffffffffu, v, o);
    return v;
}
__device__ __forceinline__ uint32_t f2tf32(float x) {
    uint32_t r;
    asm("cvt.rna.tf32.f32 %0, %1;" : "=r"(r) : "f"(x));
    return r;
}
__device__ __forceinline__ uint32_t pkbf(float x, float y) {
    __nv_bfloat162 h = __floats2bfloat162_rn(x, y);
    return *(uint32_t*)&h;
}
__device__ __forceinline__ void mma_tf32(float* d, const uint32_t* a, const uint32_t* b) {
    asm volatile(
        "mma.sync.aligned.m16n8k8.row.col.f32.tf32.tf32.f32 "
        "{%0,%1,%2,%3}, {%4,%5,%6,%7}, {%8,%9}, {%0,%1,%2,%3};"
        : "+f"(d[0]), "+f"(d[1]), "+f"(d[2]), "+f"(d[3])
        : "r"(a[0]), "r"(a[1]), "r"(a[2]), "r"(a[3]), "r"(b[0]), "r"(b[1]));
}
__device__ __forceinline__ void mma_bf16(float* d, const uint32_t* a, const uint32_t* b) {
    asm volatile(
        "mma.sync.aligned.m16n8k16.row.col.f32.bf16.bf16.f32 "
        "{%0,%1,%2,%3}, {%4,%5,%6,%7}, {%8,%9}, {%0,%1,%2,%3};"
        : "+f"(d[0]), "+f"(d[1]), "+f"(d[2]), "+f"(d[3])
        : "r"(a[0]), "r"(a[1]), "r"(a[2]), "r"(a[3]), "r"(b[0]), "r"(b[1]));
}
__device__ __forceinline__ void store2(float v0, float v1, float* p) {
    p[0] = v0; p[1] = v1;
}
__device__ __forceinline__ void store2(float v0, float v1, __nv_bfloat16* p) {
    *(__nv_bfloat162*)p = __floats2bfloat162_rn(v0, v1);
}

__global__ void zero_f(float* p, size_t n) {
    for (size_t i = (size_t)blockIdx.x * 256 + threadIdx.x; i < n;
         i += (size_t)gridDim.x * 256) p[i] = 0.f;
}
__global__ void zero_i(int* p, int n) {
    int i = blockIdx.x * 256 + threadIdx.x;
    if (i < n) p[i] = 0;
}
__global__ void copy_i(const int* a, int* b, int n) {
    int i = blockIdx.x * 256 + threadIdx.x;
    if (i < n) b[i] = a[i];
}

// ---------------------------------------------------------------------------
// Fused ABp GEMM, conflict-free stride-4 fragment layout.
// smem: As[kc(8)][m(128)][c(4)] uint2 (32KB) + Bs same (32KB) = 64KB.
// ---------------------------------------------------------------------------
__global__ __launch_bounds__(256, 2) void abp_fused(
    const float* __restrict__ h, const __nv_bfloat16* __restrict__ W1cb,
    __nv_bfloat16* __restrict__ ABh)
{
    extern __shared__ uint2 sm[];
    uint2* As = sm;            // As[kc*512 + m*4 + c]
    uint2* Bs = sm + 4096;     // Bs[kc*512 + n*4 + c]
    const int t = threadIdx.x, lane = t & 31, warp = t >> 5;
    const int row0 = blockIdx.x * 128;
    const int g = lane >> 2, c = lane & 3;
    const int wm = (warp & 3) * 32;
    const int wn = (warp >> 2) * 64;
    const int lr = t >> 1, ah = t & 1;

    // ---- A tile: fp32 -> bf16 fragment layout, once ----
    {
        const float* hp = h + (size_t)(row0 + lr) * 128 + 64 * ah;
        #pragma unroll
        for (int kq = 0; kq < 4; ++kq) {
            float f[16];
            #pragma unroll
            for (int j = 0; j < 4; ++j) *(float4*)(f + 4 * j) = *(const float4*)(hp + 16 * kq + 4 * j);
            int kc = 4 * ah + kq;
            #pragma unroll
            for (int cc = 0; cc < 4; ++cc)
                As[kc * 512 + lr * 4 + cc] =
                    make_uint2(pkbf(f[2 * cc], f[2 * cc + 1]), pkbf(f[2 * cc + 8], f[2 * cc + 9]));
        }
    }

    for (int nc = 0; nc < 8; ++nc) {
        __syncthreads();
        {
            const uint32_t* wp = (const uint32_t*)(W1cb + (size_t)(nc * 128 + lr) * 128) + 32 * ah;
            uint32_t r[32];
            #pragma unroll
            for (int j = 0; j < 8; ++j) *(uint4*)(r + 4 * j) = *(const uint4*)(wp + 4 * j);
            #pragma unroll
            for (int kq = 0; kq < 4; ++kq) {
                int kc = 4 * ah + kq;
                #pragma unroll
                for (int cc = 0; cc < 4; ++cc)
                    Bs[kc * 512 + lr * 4 + cc] = make_uint2(r[8 * kq + cc], r[8 * kq + cc + 4]);
            }
        }
        __syncthreads();

        float acc[2][8][4];
        #pragma unroll
        for (int mi = 0; mi < 2; ++mi)
            #pragma unroll
            for (int ni = 0; ni < 8; ++ni)
                #pragma unroll
                for (int j = 0; j < 4; ++j) acc[mi][ni][j] = 0.f;

        #pragma unroll
        for (int kc = 0; kc < 8; ++kc) {
            uint32_t af[2][4];
            #pragma unroll
            for (int mi = 0; mi < 2; ++mi) {
                int m = wm + mi * 16;
                uint2 u0 = As[kc * 512 + (m + g) * 4 + c];
                uint2 u1 = As[kc * 512 + (m + g + 8) * 4 + c];
                af[mi][0] = u0.x; af[mi][1] = u1.x;
                af[mi][2] = u0.y; af[mi][3] = u1.y;
            }
            uint32_t bf[8][2];
            #pragma unroll
            for (int ni = 0; ni < 8; ++ni) {
                uint2 v = Bs[kc * 512 + (wn + ni * 8 + g) * 4 + c];
                bf[ni][0] = v.x; bf[ni][1] = v.y;
            }
            #pragma unroll
            for (int mi = 0; mi < 2; ++mi)
                #pragma unroll
                for (int ni = 0; ni < 8; ++ni)
                    mma_bf16(acc[mi][ni], af[mi], bf[ni]);
        }

        #pragma unroll
        for (int mi = 0; mi < 2; ++mi) {
            #pragma unroll
            for (int ni = 0; ni < 8; ++ni) {
                int col = nc * 128 + wn + ni * 8 + 2 * c;
                #pragma unroll
                for (int half = 0; half < 2; ++half) {
                    int row = row0 + wm + mi * 16 + g + half * 8;
                    *(__nv_bfloat162*)(ABh + (size_t)row * 1024 + col) =
                        __floats2bfloat162_rn(acc[mi][ni][2 * half], acc[mi][ni][2 * half + 1]);
                }
            }
        }
    }
}

// ---------------------------------------------------------------------------
// tf32 tensor-core GEMM, double-buffered smem pipeline.
// ---------------------------------------------------------------------------
template <int BN, int EPI, typename OutT>
__global__ __launch_bounds__(256) void gemm_tf32(
    const float* __restrict__ A, int lda, const float* __restrict__ W, int ldb,
    OutT* __restrict__ C, int ldc, const float* __restrict__ bias, int K)
{
    constexpr int BM = 128, BK = 16;
    constexpr int WN = BN / 4;
    constexpr int NI = WN / 8;
    constexpr int NITB = (BK * BN) / 1024;
    __shared__ uint2    As2[2][2][BM][4];
    __shared__ uint32_t Bs[2][BK][BN + 8];
    const int row0 = blockIdx.y * BM, col0 = blockIdx.x * BN;
    const int t = threadIdx.x, lane = t & 31, warp = t >> 5;
    const int wm = (warp & 1) * 64;
    const int wn = (warp >> 1) * WN;
    const int g = lane >> 2, c = lane & 3;
    const int am = t >> 1, aks = t & 1;

    float acc[4][NI][4];
    #pragma unroll
    for (int mi = 0; mi < 4; ++mi)
        #pragma unroll
        for (int ni = 0; ni < NI; ++ni)
            #pragma unroll
            for (int j = 0; j < 4; ++j) acc[mi][ni][j] = 0.f;

    float4 ra0, ra1, rb[NITB];

    auto gload = [&](int k0) {
        const float* ap = &A[(size_t)(row0 + am) * lda + k0 + aks * 8];
        ra0 = *(const float4*)(ap);
        ra1 = *(const float4*)(ap + 4);
        #pragma unroll
        for (int it = 0; it < NITB; ++it) {
            int kk = t / (BN / 4) + it * (1024 / BN);
            int nq = (t % (BN / 4)) * 4;
            rb[it] = *(const float4*)&W[(size_t)(k0 + kk) * ldb + col0 + nq];
        }
    };
    auto sstore = [&](int p) {
        As2[p][aks][am][0] = make_uint2(f2tf32(ra0.x), f2tf32(ra1.x));
        As2[p][aks][am][1] = make_uint2(f2tf32(ra0.y), f2tf32(ra1.y));
        As2[p][aks][am][2] = make_uint2(f2tf32(ra0.z), f2tf32(ra1.z));
        As2[p][aks][am][3] = make_uint2(f2tf32(ra0.w), f2tf32(ra1.w));
        #pragma unroll
        for (int it = 0; it < NITB; ++it) {
            int kk = t / (BN / 4) + it * (1024 / BN);
            int nq = (t % (BN / 4)) * 4;
            uint32_t* dst = &Bs[p][kk][nq];
            dst[0] = f2tf32(rb[it].x); dst[1] = f2tf32(rb[it].y);
            dst[2] = f2tf32(rb[it].z); dst[3] = f2tf32(rb[it].w);
        }
    };
    auto scompute = [&](int p) {
        #pragma unroll
        for (int ks = 0; ks < 2; ++ks) {
            const int kb = ks * 8;
            uint32_t af[4][4];
            #pragma unroll
            for (int mi = 0; mi < 4; ++mi) {
                int m = wm + mi * 16;
                uint2 u0 = As2[p][ks][m + g][c];
                uint2 u1 = As2[p][ks][m + g + 8][c];
                af[mi][0] = u0.x; af[mi][1] = u1.x;
                af[mi][2] = u0.y; af[mi][3] = u1.y;
            }
            uint32_t bf[NI][2];
            #pragma unroll
            for (int ni = 0; ni < NI; ++ni) {
                int n = wn + ni * 8 + g;
                bf[ni][0] = Bs[p][kb + c][n];
                bf[ni][1] = Bs[p][kb + c + 4][n];
            }
            #pragma unroll
            for (int mi = 0; mi < 4; ++mi)
                #pragma unroll
                for (int ni = 0; ni < NI; ++ni)
                    mma_tf32(acc[mi][ni], af[mi], bf[ni]);
        }
    };

    gload(0);
    sstore(0);
    __syncthreads();
    int p = 0;
    for (int k0 = 0; k0 < K; k0 += BK) {
        const bool more = (k0 + BK < K);
        if (more) gload(k0 + BK);
        scompute(p);
        if (more) sstore(p ^ 1);
        __syncthreads();
        p ^= 1;
    }
    #pragma unroll
    for (int mi = 0; mi < 4; ++mi) {
        #pragma unroll
        for (int ni = 0; ni < NI; ++ni) {
            int row = row0 + wm + mi * 16 + g;
            int col = col0 + wn + ni * 8 + 2 * c;
            #pragma unroll
            for (int half = 0; half < 2; ++half) {
                int r = row + half * 8;
                float v0 = acc[mi][ni][2 * half + 0];
                float v1 = acc[mi][ni][2 * half + 1];
                if (EPI >= 1) { v0 += bias[col]; v1 += bias[col + 1]; }
                if (EPI == 2) { v0 = fmaxf(v0, 0.f); v1 = fmaxf(v1, 0.f); }
                size_t off = (size_t)r * ldc + col;
                if (EPI == 3) { C[off] += v0; C[off + 1] += v1; }
                else          store2(v0, v1, &C[off]);
            }
        }
    }
}

// ---------------------------------------------------------------------------
// Fused update GEMM: hid = relu( catA(640) @ W1u(640x256) + ub1
//                                + di*vm + dz*vr ), di/dz from CSR ptrs.
// Same structure as gemm_tf32 BN=128; grid (2, N/128).
// ---------------------------------------------------------------------------
__global__ __launch_bounds__(256) void gemm_upd(
    const float* __restrict__ A, const float* __restrict__ W,
    float* __restrict__ C, const float* __restrict__ bias,
    const int* __restrict__ pin, const int* __restrict__ pout,
    const float* __restrict__ vm, const float* __restrict__ vr)
{
    constexpr int BN = 128, BM = 128, BK = 16, NI = 4, K = 640;
    constexpr int lda = 640, ldb = 256, ldc = 256;
    __shared__ uint2    As2[2][2][BM][4];
    __shared__ uint32_t Bs[2][BK][BN + 8];
    const int row0 = blockIdx.y * BM, col0 = blockIdx.x * BN;
    const int t = threadIdx.x, lane = t & 31, warp = t >> 5;
    const int wm = (warp & 1) * 64;
    const int wn = (warp >> 1) * 32;
    const int g = lane >> 2, c = lane & 3;
    const int am = t >> 1, aks = t & 1;

    float acc[4][NI][4];
    #pragma unroll
    for (int mi = 0; mi < 4; ++mi)
        #pragma unroll
        for (int ni = 0; ni < NI; ++ni)
            #pragma unroll
            for (int j = 0; j < 4; ++j) acc[mi][ni][j] = 0.f;

    float4 ra0, ra1, rb[2];

    auto gload = [&](int k0) {
        const float* ap = &A[(size_t)(row0 + am) * lda + k0 + aks * 8];
        ra0 = *(const float4*)(ap);
        ra1 = *(const float4*)(ap + 4);
        #pragma unroll
        for (int it = 0; it < 2; ++it) {
            int kk = t / 32 + it * 8;
            int nq = (t % 32) * 4;
            rb[it] = *(const float4*)&W[(size_t)(k0 + kk) * ldb + col0 + nq];
        }
    };
    auto sstore = [&](int p) {
        As2[p][aks][am][0] = make_uint2(f2tf32(ra0.x), f2tf32(ra1.x));
        As2[p][aks][am][1] = make_uint2(f2tf32(ra0.y), f2tf32(ra1.y));
        As2[p][aks][am][2] = make_uint2(f2tf32(ra0.z), f2tf32(ra1.z));
        As2[p][aks][am][3] = make_uint2(f2tf32(ra0.w), f2tf32(ra1.w));
        #pragma unroll
        for (int it = 0; it < 2; ++it) {
            int kk = t / 32 + it * 8;
            int nq = (t % 32) * 4;
            uint32_t* dst = &Bs[p][kk][nq];
            dst[0] = f2tf32(rb[it].x); dst[1] = f2tf32(rb[it].y);
            dst[2] = f2tf32(rb[it].z); dst[3] = f2tf32(rb[it].w);
        }
    };
    auto scompute = [&](int p) {
        #pragma unroll
        for (int ks = 0; ks < 2; ++ks) {
            const int kb = ks * 8;
            uint32_t af[4][4];
            #pragma unroll
            for (int mi = 0; mi < 4; ++mi) {
                int m = wm + mi * 16;
                uint2 u0 = As2[p][ks][m + g][c];
                uint2 u1 = As2[p][ks][m + g + 8][c];
                af[mi][0] = u0.x; af[mi][1] = u1.x;
                af[mi][2] = u0.y; af[mi][3] = u1.y;
            }
            uint32_t bf[NI][2];
            #pragma unroll
            for (int ni = 0; ni < NI; ++ni) {
                int n = wn + ni * 8 + g;
                bf[ni][0] = Bs[p][kb + c][n];
                bf[ni][1] = Bs[p][kb + c + 4][n];
            }
            #pragma unroll
            for (int mi = 0; mi < 4; ++mi)
                #pragma unroll
                for (int ni = 0; ni < NI; ++ni)
                    mma_tf32(acc[mi][ni], af[mi], bf[ni]);
        }
    };

    gload(0);
    sstore(0);
    __syncthreads();
    int p = 0;
    for (int k0 = 0; k0 < K; k0 += BK) {
        const bool more = (k0 + BK < K);
        if (more) gload(k0 + BK);
        scompute(p);
        if (more) sstore(p ^ 1);
        __syncthreads();
        p ^= 1;
    }
    #pragma unroll
    for (int mi = 0; mi < 4; ++mi) {
        #pragma unroll
        for (int half = 0; half < 2; ++half) {
            int r = row0 + wm + mi * 16 + g + half * 8;
            float di = (float)(pin [r + 1] - pin [r]);
            float dz = (float)(pout[r + 1] - pout[r]);
            #pragma unroll
            for (int ni = 0; ni < NI; ++ni) {
                int col = col0 + wn + ni * 8 + 2 * c;
                float v0 = acc[mi][ni][2 * half + 0]
                         + bias[col]     + di * vm[col]     + dz * vr[col];
                float v1 = acc[mi][ni][2 * half + 1]
                         + bias[col + 1] + di * vm[col + 1] + dz * vr[col + 1];
                store2(fmaxf(v0, 0.f), fmaxf(v1, 0.f), &C[(size_t)r * ldc + col]);
            }
        }
    }
}

__global__ void pack_w1cb(const float* __restrict__ m1, const float* __restrict__ r1,
                          __nv_bfloat16* __restrict__ w) {
    int i = blockIdx.x * 256 + threadIdx.x;
    if (i >= 1024 * 128) return;
    int n = i >> 7, k = i & 127;
    float v;
    if (n < 256)      v = m1[k * 256 + n];
    else if (n < 512) v = m1[(128 + k) * 256 + (n - 256)];
    else if (n < 768) v = r1[k * 256 + (n - 512)];
    else              v = r1[(128 + k) * 256 + (n - 768)];
    w[i] = __float2bfloat16(v);
}
__global__ void pack_w2cat(const float* __restrict__ m2, const float* __restrict__ r2,
                           float* __restrict__ w) {
    int i = blockIdx.x * 256 + threadIdx.x;
    if (i >= 512 * 128) return;
    int k = i >> 7, j = i & 127;
    w[i] = (k < 256) ? m2[k * 128 + j] : r2[(k - 256) * 128 + j];
}
__global__ void pack_u1bot(const float* __restrict__ u1, float* __restrict__ W1u) {
    int i = blockIdx.x * 256 + threadIdx.x;
    if (i >= 128 * 256) return;
    W1u[512 * 256 + i] = u1[128 * 256 + i];
}
__global__ void vmvr_kernel(const float* __restrict__ u1, const float* __restrict__ mb2,
                            const float* __restrict__ rb2, float* __restrict__ vm,
                            float* __restrict__ vr) {
    int j = threadIdx.x;
    float sm = 0.f, sr = 0.f;
    for (int k = 0; k < 128; ++k) {
        float u = u1[k * 256 + j];
        sm += mb2[k] * u;
        sr += rb2[k] * u;
    }
    vm[j] = sm; vr[j] = sr;
}
__global__ void pack_wecat(const float* __restrict__ m1, const float* __restrict__ r1,
                           const float* __restrict__ mb1, const float* __restrict__ rb1,
                           float* __restrict__ w, float* __restrict__ bcat) {
    int i = blockIdx.x * 256 + threadIdx.x;
    if (i < 64 * 512) {
        int k = i >> 9, j = i & 511;
        w[i] = (j < 256) ? m1[(256 + k) * 256 + j] : r1[(256 + k) * 256 + (j - 256)];
    }
    if (i < 512) bcat[i] = (i < 256) ? mb1[i] : rb1[i - 256];
}

__global__ void deg_count(const int* __restrict__ fr, const int* __restrict__ to,
                          int* din, int* dout, int E) {
    int e = blockIdx.x * 256 + threadIdx.x;
    if (e < E) { atomicAdd(&din[to[e]], 1); atomicAdd(&dout[fr[e]], 1); }
}
__global__ void exscan_kernel(const int* __restrict__ in, int* __restrict__ out, int n) {
    __shared__ int buf[1024];
    __shared__ int carry_s;
    int t = threadIdx.x;
    if (t == 0) carry_s = 0;
    __syncthreads();
    for (int base = 0; base < n; base += 1024) {
        int i = base + t;
        int v = (i < n) ? in[i] : 0;
        buf[t] = v;
        __syncthreads();
        for (int d = 1; d < 1024; d <<= 1) {
            int x = (t >= d) ? buf[t - d] : 0;
            __syncthreads();
            buf[t] += x;
            __syncthreads();
        }
        if (i < n) out[i] = carry_s + buf[t] - v;
        int tot = buf[1023];
        __syncthreads();
        if (t == 0) carry_s += tot;
        __syncthreads();
    }
    if (t == 0) out[n] = carry_s;
}
__global__ void csr_fill(const int* __restrict__ fr, const int* __restrict__ to,
                         int* cin, int* cout, int* iin, int* iout, int E) {
    int e = blockIdx.x * 256 + threadIdx.x;
    if (e < E) {
        int s  = atomicAdd(&cin [to[e]], 1); iin [s]  = e;
        int s2 = atomicAdd(&cout[fr[e]], 1); iout[s2] = e;
    }
}

__global__ __launch_bounds__(256) void permute_eenc(
    const float* __restrict__ eenc, const int* __restrict__ idx,
    const int* __restrict__ endp, float* __restrict__ out,
    int* __restrict__ ocsr, int E)
{
    int j = blockIdx.x * 8 + (threadIdx.x >> 5);
    if (j >= E) return;
    int lane = threadIdx.x & 31;
    int e = idx[j];
    if (lane == 0) ocsr[j] = endp[e];
    const float2* s2 = (const float2*)(eenc + (size_t)e * 64);
    float2* d2 = (float2*)(out + (size_t)j * 64);
    d2[lane] = s2[lane];
}

__global__ __launch_bounds__(256) void agg_kernel(
    const int* __restrict__ ptr, const int* __restrict__ ocsr,
    const __nv_bfloat162* __restrict__ AB, int aoff, int boff,
    const __nv_bfloat162* __restrict__ ecsr,
    float* __restrict__ catA, int ooff, int Nn)
{
    int n = (blockIdx.x * blockDim.x + threadIdx.x) >> 5;
    int lane = threadIdx.x & 31;
    if (n >= Nn) return;
    float bv[8], acc[8];
    const __nv_bfloat162* bp = AB + (size_t)n * 512 + boff;
    #pragma unroll
    for (int k = 0; k < 4; ++k) {
        float2 b2 = __bfloat1622float2(bp[lane + 32 * k]);
        bv[2 * k] = b2.x; bv[2 * k + 1] = b2.y;
        acc[2 * k] = 0.f; acc[2 * k + 1] = 0.f;
    }
    int s = ptr[n], e1 = ptr[n + 1];
    for (int j = s; j < e1; ++j) {
        int o = ocsr[j];
        const __nv_bfloat162* ap = AB + (size_t)o * 512 + aoff;
        const __nv_bfloat162* ep = ecsr + (size_t)j * 128;
        #pragma unroll
        for (int k = 0; k < 4; ++k) {
            float2 a2 = __bfloat1622float2(ap[lane + 32 * k]);
            float2 e2 = __bfloat1622float2(ep[lane + 32 * k]);
            acc[2 * k]     += fmaxf(a2.x + e2.x + bv[2 * k],     0.f);
            acc[2 * k + 1] += fmaxf(a2.y + e2.y + bv[2 * k + 1], 0.f);
        }
    }
    float2* op = (float2*)(catA + (size_t)n * 640 + ooff);
    #pragma unroll
    for (int k = 0; k < 4; ++k) op[lane + 32 * k] = make_float2(acc[2 * k], acc[2 * k + 1]);
}

__global__ void copy_h_kernel(const float* __restrict__ h, float* __restrict__ catA) {
    int n = blockIdx.x, t = threadIdx.x;
    catA[(size_t)n * 640 + 512 + t] = h[(size_t)n * 128 + t];
}

__global__ void build_sizes(const int* __restrict__ qs, const int* __restrict__ cs,
                            int* __restrict__ sizes, int B2) {
    int i = blockIdx.x * 256 + threadIdx.x;
    if (i < B2) sizes[i] = (i & 1) ? cs[i >> 1] : qs[i >> 1];
}
__global__ void scatter_kernel(const float* __restrict__ h, const int* __restrict__ gidx,
                               const int* __restrict__ starts, float* __restrict__ st) {
    int n = blockIdx.x, t = threadIdx.x;
    int g = gidx[n];
    int pos = n - starts[g];
    st[((size_t)g * 128 + pos) * 128 + t] = h[(size_t)n * 128 + t];
}
__global__ void mask_kernel(float* __restrict__ tt, const int* __restrict__ qs,
                            const int* __restrict__ cs) {
    int r = blockIdx.x, j = threadIdx.x;
    int b = r >> 8, side = (r >> 7) & 1, pos = r & 127;
    int sz = side ? cs[b] : qs[b];
    if (pos >= sz) tt[(size_t)r * 128 + j] = 0.f;
}

__global__ __launch_bounds__(256) void pair_gemm_kernel(const float* __restrict__ tt,
                                                        float* __restrict__ la) {
    int b = blockIdx.x;
    const float* Aq = tt + (size_t)(2 * b)     * 16384;
    const float* Ac = tt + (size_t)(2 * b + 1) * 16384;
    __shared__ float As[16][132], Bs[16][132];
    int t = threadIdx.x, tx = t & 15, ty = t >> 4;
    float acc[8][8];
    #pragma unroll
    for (int i = 0; i < 8; ++i)
        #pragma unroll
        for (int j = 0; j < 8; ++j) acc[i][j] = 0.f;
    for (int k0 = 0; k0 < 128; k0 += 16) {
        #pragma unroll
        for (int it = 0; it < 2; ++it) {
            int m = (t >> 2) + it * 64, kq = (t & 3) * 4;
            float4 v = *(const float4*)&Aq[m * 128 + k0 + kq];
            As[kq][m] = v.x; As[kq + 1][m] = v.y; As[kq + 2][m] = v.z; As[kq + 3][m] = v.w;
            float4 w = *(const float4*)&Ac[m * 128 + k0 + kq];
            Bs[kq][m] = w.x; Bs[kq + 1][m] = w.y; Bs[kq + 2][m] = w.z; Bs[kq + 3][m] = w.w;
        }
        __syncthreads();
        #pragma unroll
        for (int k = 0; k < 16; ++k) {
            float a[8], bv[8];
            *(float4*)(a)      = *(const float4*)&As[k][ty * 8];
            *(float4*)(a + 4)  = *(const float4*)&As[k][ty * 8 + 4];
            *(float4*)(bv)     = *(const float4*)&Bs[k][tx * 8];
            *(float4*)(bv + 4) = *(const float4*)&Bs[k][tx * 8 + 4];
            #pragma unroll
            for (int i = 0; i < 8; ++i)
                #pragma unroll
                for (int j = 0; j < 8; ++j) acc[i][j] += a[i] * bv[j];
        }
        __syncthreads();
    }
    float* dst = la + (size_t)b * 16384;
    #pragma unroll
    for (int i = 0; i < 8; ++i)
        #pragma unroll
        for (int j = 0; j < 8; ++j)
            dst[(ty * 8 + i) * 128 + tx * 8 + j] = acc[i][j] * 10.0f;
}

__global__ __launch_bounds__(256) void sinkhorn_kernel(float* __restrict__ la_g,
                                                       const int* __restrict__ qs,
                                                       const int* __restrict__ cs) {
    extern __shared__ float P[];
    const int b = blockIdx.x;
    const int R = qs[b], C = cs[b];
    const float wR = (float)(128 - R), wC = (float)(128 - C);
    const int RT = (R < 128) ? R + 1 : 128;
    const int CT = (C < 128) ? C + 1 : 128;
    float* src = la_g + (size_t)b * 16384;
    const int t = threadIdx.x;
    for (int i = t; i < RT * CT; i += 256) {
        int q = i / CT, c = i % CT;
        P[q * 131 + c] = (q < R && c < C) ? src[q * 128 + c] : 0.f;
    }
    __syncthreads();
    const int warp = t >> 5, lane = t & 31;
    for (int iter = 0; iter < 20; ++iter) {
        for (int q = warp; q < RT; q += 8) {
            float m = -1e30f;
            for (int c = lane; c < CT; c += 32) m = fmaxf(m, P[q * 131 + c]);
            m = warp_max(m);
            float s = 0.f;
            for (int c = lane; c < CT; c += 32) {
                float w = (c == C) ? wC : 1.f;
                s += w * __expf(P[q * 131 + c] - m);
            }
            s = warp_sum(s);
            float lse = m + __logf(s);
            for (int c = lane; c < CT; c += 32) P[q * 131 + c] -= lse;
        }
        __syncthreads();
        for (int c = warp; c < CT; c += 8) {
            float m = -1e30f;
            for (int q = lane; q < RT; q += 32) m = fmaxf(m, P[q * 131 + c]);
            m = warp_max(m);
            float s = 0.f;
            for (int q = lane; q < RT; q += 32) {
                float w = (q == R) ? wR : 1.f;
                s += w * __expf(P[q * 131 + c] - m);
            }
            s = warp_sum(s);
            float lse = m + __logf(s);
            for (int q = lane; q < RT; q += 32) P[q * 131 + c] -= lse;
        }
        __syncthreads();
    }
    for (int i = t; i < 16384; i += 256) {
        int q = i >> 7, c = i & 127;
        int qe = (q < R) ? q : R;
        int ce = (c < C) ? c : C;
        src[i] = __expf(P[qe * 131 + ce]);
    }
}

__global__ __launch_bounds__(256) void score_kernel(const float* __restrict__ plan,
                                                    const float* __restrict__ stacked,
                                                    float* __restrict__ out) {
    int b = blockIdx.x;
    const float* P  = plan    + (size_t)b * 16384;
    const float* Q  = stacked + (size_t)(2 * b)     * 16384;
    const float* Cm = stacked + (size_t)(2 * b + 1) * 16384;
    __shared__ float As[16][132], Bs[16][132];
    int t = threadIdx.x, tx = t & 15, ty = t >> 4;
    float acc[8][8];
    #pragma unroll
    for (int i = 0; i < 8; ++i)
        #pragma unroll
        for (int j = 0; j < 8; ++j) acc[i][j] = 0.f;
    for (int k0 = 0; k0 < 128; k0 += 16) {
        #pragma unroll
        for (int it = 0; it < 2; ++it) {
            int m = (t >> 2) + it * 64, kq = (t & 3) * 4;
            float4 v = *(const float4*)&P[m * 128 + k0 + kq];
            As[kq][m] = v.x; As[kq + 1][m] = v.y; As[kq + 2][m] = v.z; As[kq + 3][m] = v.w;
        }
        #pragma unroll
        for (int it = 0; it < 2; ++it) {
            int kk = (t >> 5) + it * 8, nq = (t & 31) * 4;
            *(float4*)&Bs[kk][nq] = *(const float4*)&Cm[(k0 + kk) * 128 + nq];
        }
        __syncthreads();
        #pragma unroll
        for (int k = 0; k < 16; ++k) {
            float a[8], bv[8];
            *(float4*)(a)      = *(const float4*)&As[k][ty * 8];
            *(float4*)(a + 4)  = *(const float4*)&As[k][ty * 8 + 4];
            *(float4*)(bv)     = *(const float4*)&Bs[k][tx * 8];
            *(float4*)(bv + 4) = *(const float4*)&Bs[k][tx * 8 + 4];
            #pragma unroll
            for (int i = 0; i < 8; ++i)
                #pragma unroll
                for (int j = 0; j < 8; ++j) acc[i][j] += a[i] * bv[j];
        }
        __syncthreads();
    }
    float s = 0.f;
    #pragma unroll
    for (int i = 0; i < 8; ++i)
        #pragma unroll
        for (int j = 0; j < 8; ++j)
            s += fmaxf(Q[(ty * 8 + i) * 128 + tx * 8 + j] - acc[i][j], 0.f);
    s = warp_sum(s);
    __shared__ float red[8];
    if ((t & 31) == 0) red[t >> 5] = s;
    __syncthreads();
    if (t == 0) {
        float tot = 0.f;
        #pragma unroll
        for (int i = 0; i < 8; ++i) tot += red[i];
        out[b] = -tot;
    }
}

template <typename T>
static T* sym(const void* s) { void* p = nullptr; cudaGetSymbolAddress(&p, s); return (T*)p; }

extern "C" void kernel_launch(void* const* d_in, const int* in_sizes, int n_in,
                              void* d_out, int out_size) {
    const float* nf  = (const float*)d_in[0];
    const float* ef  = (const float*)d_in[1];
    const float* enW = (const float*)d_in[2];  const float* enB = (const float*)d_in[3];
    const float* eeW = (const float*)d_in[4];  const float* eeB = (const float*)d_in[5];
    const float* m1  = (const float*)d_in[6];  const float* mb1 = (const float*)d_in[7];
    const float* m2  = (const float*)d_in[8];  const float* mb2 = (const float*)d_in[9];
    const float* r1  = (const float*)d_in[10]; const float* rb1 = (const float*)d_in[11];
    const float* r2  = (const float*)d_in[12]; const float* rb2 = (const float*)d_in[13];
    const float* u1  = (const float*)d_in[14]; const float* ub1 = (const float*)d_in[15];
    const float* u2  = (const float*)d_in[16]; const float* ub2 = (const float*)d_in[17];
    const float* f1  = (const float*)d_in[18]; const float* f1b = (const float*)d_in[19];
    const float* f2  = (const float*)d_in[20]; const float* f2b = (const float*)d_in[21];
    const int* fr  = (const int*)d_in[22];
    const int* to  = (const int*)d_in[23];
    const int* gix = (const int*)d_in[24];
    const int* qs  = (const int*)d_in[25];
    const int* cs  = (const int*)d_in[26];
    const int E  = in_sizes[22];
    const int N  = in_sizes[24];
    const int B  = in_sizes[25];
    const int B2 = 2 * B;
    float* out = (float*)d_out;

    float* h    = sym<float>(g_h);    float* eenc = sym<float>(g_eenc);
    float* eP   = sym<float>(g_eP);
    __nv_bfloat16* ABh = sym<__nv_bfloat16>(g_ABh);
    __nv_bfloat16* eMc = sym<__nv_bfloat16>(g_eMc);
    __nv_bfloat16* eRc = sym<__nv_bfloat16>(g_eRc);
    __nv_bfloat16* W1cb = sym<__nv_bfloat16>(g_W1cb);
    float* catA = sym<float>(g_catA);
    float* hid  = sym<float>(g_hid);  float* tt   = sym<float>(g_t);
    float* stk  = sym<float>(g_stk);  float* la   = sym<float>(g_la);
    float* W2c  = sym<float>(g_W2cat);
    float* W1u  = sym<float>(g_W1u);
    float* vm   = sym<float>(g_vm);   float* vr   = sym<float>(g_vr);
    float* Wec  = sym<float>(g_Wecat); float* bec = sym<float>(g_becat);
    int* sizes = sym<int>(g_sizes); int* starts = sym<int>(g_starts);
    int* din = sym<int>(g_din);   int* dout = sym<int>(g_dout);
    int* pin = sym<int>(g_pin);   int* pout = sym<int>(g_pout);
    int* cin = sym<int>(g_cin);   int* cout = sym<int>(g_cout);
    int* iin = sym<int>(g_iin);   int* iout = sym<int>(g_iout);
    int* oin = sym<int>(g_oin);   int* oout = sym<int>(g_oout);
    float* ePa = eP;
    float* ePb = eP + (size_t)EMAX * 64;

    const int ABP_SMEM = 2 * 4096 * 8;  // 64 KB

    static bool attr_set = false;
    if (!attr_set) {
        cudaFuncSetAttribute(sinkhorn_kernel,
                             cudaFuncAttributeMaxDynamicSharedMemorySize, 129 * 131 * 4);
        cudaFuncSetAttribute(abp_fused,
                             cudaFuncAttributeMaxDynamicSharedMemorySize, ABP_SMEM);
        attr_set = true;
    }

    // ---- launches 1-6; #4 (= ncu capture) is abp_fused ----
    gemm_tf32<128, 1, float><<<dim3(1, N / 128), 256>>>(nf, 32, enW, 128, h, 128, enB, 32);
    pack_w1cb<<<(1024 * 128 + 255) / 256, 256>>>(m1, r1, W1cb);
    pack_wecat<<<(64 * 512 + 255) / 256, 256>>>(m1, r1, mb1, rb1, Wec, bec);
    abp_fused<<<N / 128, 256, ABP_SMEM>>>(h, W1cb, ABh);
    pack_w2cat<<<(512 * 128 + 255) / 256, 256>>>(m2, r2, W2c);
    gemm_tf32<64, 1, float><<<dim3(1, E / 128), 256>>>(ef, 16, eeW, 64, eenc, 64, eeB, 16);

    // ---- fused-update precompute: W1u = [W2c@u1_top ; u1_bot], vm, vr ----
    gemm_tf32<128, 0, float><<<dim3(2, 4), 256>>>(W2c, 128, u1, 256, W1u, 256, nullptr, 128);
    pack_u1bot<<<(128 * 256 + 255) / 256, 256>>>(u1, W1u);
    vmvr_kernel<<<1, 256>>>(u1, mb2, rb2, vm, vr);

    // ---- graph structure ----
    zero_i<<<(N + 255) / 256, 256>>>(din, N);
    zero_i<<<(N + 255) / 256, 256>>>(dout, N);
    build_sizes<<<(B2 + 255) / 256, 256>>>(qs, cs, sizes, B2);
    exscan_kernel<<<1, 1024>>>(sizes, starts, B2);
    deg_count<<<(E + 255) / 256, 256>>>(fr, to, din, dout, E);
    exscan_kernel<<<1, 1024>>>(din, pin, N);
    exscan_kernel<<<1, 1024>>>(dout, pout, N);
    copy_i<<<(N + 255) / 256, 256>>>(pin, cin, N);
    copy_i<<<(N + 255) / 256, 256>>>(pout, cout, N);
    csr_fill<<<(E + 255) / 256, 256>>>(fr, to, cin, cout, iin, iout, E);

    // ---- edge constants: permute eenc, GEMM directly to bf16 CSR ----
    permute_eenc<<<(E + 7) / 8, 256>>>(eenc, iin,  fr, ePa, oin,  E);
    permute_eenc<<<(E + 7) / 8, 256>>>(eenc, iout, to, ePb, oout, E);
    gemm_tf32<128, 1, __nv_bfloat16><<<dim3(2, E / 128), 256>>>(
        ePa, 64, Wec, 512, eMc, 256, bec, 64);
    gemm_tf32<128, 1, __nv_bfloat16><<<dim3(2, E / 128), 256>>>(
        ePb, 64, Wec + 256, 512, eRc, 256, bec + 256, 64);

    // ---- propagation rounds (round 0's ABp already done above) ----
    for (int r = 0; r < 5; ++r) {
        if (r > 0)
            abp_fused<<<N / 128, 256, ABP_SMEM>>>(h, W1cb, ABh);
        agg_kernel<<<(N + 7) / 8, 256>>>(pin,  oin,  (const __nv_bfloat162*)ABh, 0,   128,
                                         (const __nv_bfloat162*)eMc, catA, 0,   N);
        agg_kernel<<<(N + 7) / 8, 256>>>(pout, oout, (const __nv_bfloat162*)ABh, 256, 384,
                                         (const __nv_bfloat162*)eRc, catA, 256, N);
        copy_h_kernel<<<N, 128>>>(h, catA);
        gemm_upd<<<dim3(2, N / 128), 256>>>(catA, W1u, hid, ub1, pin, pout, vm, vr);
        gemm_tf32<128, 3, float><<<dim3(1, N / 128), 256>>>(hid, 256, u2, 128, h, 128, ub2, 256);
    }

    // ---- stack + transform ----
    zero_f<<<2048, 256>>>(stk, (size_t)B2 * 16384);
    scatter_kernel<<<N, 128>>>(h, gix, starts, stk);
    gemm_tf32<128, 2, float><<<dim3(1, B2 * 128 / 128), 256>>>(stk, 128, f1, 128, hid, 128, f1b, 128);
    gemm_tf32<128, 1, float><<<dim3(1, B2 * 128 / 128), 256>>>(hid, 128, f2, 128, tt, 128, f2b, 128);
    mask_kernel<<<B2 * 128, 128>>>(tt, qs, cs);

    // ---- sinkhorn + score ----
    pair_gemm_kernel<<<B, 256>>>(tt, la);
    sinkhorn_kernel<<<B, 256, 129 * 131 * 4>>>(la, qs, cs);
    score_kernel<<<B, 256>>>(la, stk, out);
}

// round 14
// speedup vs baseline: 1.0723x; 1.0574x over previous
#include <cuda_runtime.h>
#include <cuda_bf16.h>
#include <cstdint>
#include <cstddef>

#define NMAX 98304
#define EMAX 786432
#define BMAX 512

__device__ float g_h   [(size_t)NMAX * 128];
__device__ float g_eenc[(size_t)EMAX * 64];
__device__ float g_eP  [(size_t)EMAX * 128];
__device__ __nv_bfloat16 g_ABh [(size_t)NMAX * 1024];
__device__ __nv_bfloat16 g_eMc [(size_t)EMAX * 256];
__device__ __nv_bfloat16 g_eRc [(size_t)EMAX * 256];
__device__ __nv_bfloat16 g_W1cb[1024 * 128];
__device__ float g_catA[(size_t)NMAX * 640];
__device__ float g_hid [(size_t)NMAX * 256];
__device__ float g_t   [(size_t)BMAX * 2 * 128 * 128];
__device__ float g_stk [(size_t)BMAX * 2 * 128 * 128];
__device__ float g_la  [(size_t)BMAX * 128 * 128];
__device__ float g_W2cat[512 * 128];
__device__ float g_W1u [640 * 256];
__device__ float g_vm  [256];
__device__ float g_vr  [256];
__device__ float g_Wecat[64 * 512];
__device__ float g_becat[512];
__device__ int   g_sizes [2 * BMAX];
__device__ int   g_starts[2 * BMAX + 1];
__device__ int   g_din [NMAX];
__device__ int   g_dout[NMAX];
__device__ int   g_pin [NMAX + 1];
__device__ int   g_pout[NMAX + 1];
__device__ int   g_cin [NMAX];
__device__ int   g_cout[NMAX];
__device__ int   g_iin [EMAX];
__device__ int   g_iout[EMAX];
__device__ int   g_oin [EMAX];
__device__ int   g_oout[EMAX];

__device__ __forceinline__ float warp_max(float v) {
    #pragma unroll
    for (int o = 16; o; o >>= 1) v = fmaxf(v, __shfl_xor_sync(0xffffffffu, v, o));
    return v;
}
__device__ __forceinline__ float warp_sum(float v) {
    #pragma unroll
    for (int o = 16; o; o >>= 1) v += __shfl_xor_sync(0xffffffffu, v, o);
    return v;
}
__device__ __forceinline__ uint32_t f2tf32(float x) {
    uint32_t r;
    asm("cvt.rna.tf32.f32 %0, %1;" : "=r"(r) : "f"(x));
    return r;
}
__device__ __forceinline__ uint32_t pkbf(float x, float y) {
    __nv_bfloat162 h = __floats2bfloat162_rn(x, y);
    return *(uint32_t*)&h;
}
__device__ __forceinline__ void mma_tf32(float* d, const uint32_t* a, const uint32_t* b) {
    asm volatile(
        "mma.sync.aligned.m16n8k8.row.col.f32.tf32.tf32.f32 "
        "{%0,%1,%2,%3}, {%4,%5,%6,%7}, {%8,%9}, {%0,%1,%2,%3};"
        : "+f"(d[0]), "+f"(d[1]), "+f"(d[2]), "+f"(d[3])
        : "r"(a[0]), "r"(a[1]), "r"(a[2]), "r"(a[3]), "r"(b[0]), "r"(b[1]));
}
__device__ __forceinline__ void mma_bf16(float* d, const uint32_t* a, const uint32_t* b) {
    asm volatile(
        "mma.sync.aligned.m16n8k16.row.col.f32.bf16.bf16.f32 "
        "{%0,%1,%2,%3}, {%4,%5,%6,%7}, {%8,%9}, {%0,%1,%2,%3};"
        : "+f"(d[0]), "+f"(d[1]), "+f"(d[2]), "+f"(d[3])
        : "r"(a[0]), "r"(a[1]), "r"(a[2]), "r"(a[3]), "r"(b[0]), "r"(b[1]));
}
__device__ __forceinline__ void store2(float v0, float v1, float* p) {
    p[0] = v0; p[1] = v1;
}
__device__ __forceinline__ void store2(float v0, float v1, __nv_bfloat16* p) {
    *(__nv_bfloat162*)p = __floats2bfloat162_rn(v0, v1);
}

__global__ void zero_f(float* p, size_t n) {
    for (size_t i = (size_t)blockIdx.x * 256 + threadIdx.x; i < n;
         i += (size_t)gridDim.x * 256) p[i] = 0.f;
}
__global__ void zero_i(int* p, int n) {
    int i = blockIdx.x * 256 + threadIdx.x;
    if (i < n) p[i] = 0;
}
__global__ void copy_i(const int* a, int* b, int n) {
    int i = blockIdx.x * 256 + threadIdx.x;
    if (i < n) b[i] = a[i];
}

// ---------------------------------------------------------------------------
// Fused ABp GEMM, conflict-free stride-4 fragment layout.
// ---------------------------------------------------------------------------
__global__ __launch_bounds__(256, 2) void abp_fused(
    const float* __restrict__ h, const __nv_bfloat16* __restrict__ W1cb,
    __nv_bfloat16* __restrict__ ABh)
{
    extern __shared__ uint2 sm[];
    uint2* As = sm;
    uint2* Bs = sm + 4096;
    const int t = threadIdx.x, lane = t & 31, warp = t >> 5;
    const int row0 = blockIdx.x * 128;
    const int g = lane >> 2, c = lane & 3;
    const int wm = (warp & 3) * 32;
    const int wn = (warp >> 2) * 64;
    const int lr = t >> 1, ah = t & 1;

    {
        const float* hp = h + (size_t)(row0 + lr) * 128 + 64 * ah;
        #pragma unroll
        for (int kq = 0; kq < 4; ++kq) {
            float f[16];
            #pragma unroll
            for (int j = 0; j < 4; ++j) *(float4*)(f + 4 * j) = *(const float4*)(hp + 16 * kq + 4 * j);
            int kc = 4 * ah + kq;
            #pragma unroll
            for (int cc = 0; cc < 4; ++cc)
                As[kc * 512 + lr * 4 + cc] =
                    make_uint2(pkbf(f[2 * cc], f[2 * cc + 1]), pkbf(f[2 * cc + 8], f[2 * cc + 9]));
        }
    }

    for (int nc = 0; nc < 8; ++nc) {
        __syncthreads();
        {
            const uint32_t* wp = (const uint32_t*)(W1cb + (size_t)(nc * 128 + lr) * 128) + 32 * ah;
            uint32_t r[32];
            #pragma unroll
            for (int j = 0; j < 8; ++j) *(uint4*)(r + 4 * j) = *(const uint4*)(wp + 4 * j);
            #pragma unroll
            for (int kq = 0; kq < 4; ++kq) {
                int kc = 4 * ah + kq;
                #pragma unroll
                for (int cc = 0; cc < 4; ++cc)
                    Bs[kc * 512 + lr * 4 + cc] = make_uint2(r[8 * kq + cc], r[8 * kq + cc + 4]);
            }
        }
        __syncthreads();

        float acc[2][8][4];
        #pragma unroll
        for (int mi = 0; mi < 2; ++mi)
            #pragma unroll
            for (int ni = 0; ni < 8; ++ni)
                #pragma unroll
                for (int j = 0; j < 4; ++j) acc[mi][ni][j] = 0.f;

        #pragma unroll
        for (int kc = 0; kc < 8; ++kc) {
            uint32_t af[2][4];
            #pragma unroll
            for (int mi = 0; mi < 2; ++mi) {
                int m = wm + mi * 16;
                uint2 u0 = As[kc * 512 + (m + g) * 4 + c];
                uint2 u1 = As[kc * 512 + (m + g + 8) * 4 + c];
                af[mi][0] = u0.x; af[mi][1] = u1.x;
                af[mi][2] = u0.y; af[mi][3] = u1.y;
            }
            uint32_t bf[8][2];
            #pragma unroll
            for (int ni = 0; ni < 8; ++ni) {
                uint2 v = Bs[kc * 512 + (wn + ni * 8 + g) * 4 + c];
                bf[ni][0] = v.x; bf[ni][1] = v.y;
            }
            #pragma unroll
            for (int mi = 0; mi < 2; ++mi)
                #pragma unroll
                for (int ni = 0; ni < 8; ++ni)
                    mma_bf16(acc[mi][ni], af[mi], bf[ni]);
        }

        #pragma unroll
        for (int mi = 0; mi < 2; ++mi) {
            #pragma unroll
            for (int ni = 0; ni < 8; ++ni) {
                int col = nc * 128 + wn + ni * 8 + 2 * c;
                #pragma unroll
                for (int half = 0; half < 2; ++half) {
                    int row = row0 + wm + mi * 16 + g + half * 8;
                    *(__nv_bfloat162*)(ABh + (size_t)row * 1024 + col) =
                        __floats2bfloat162_rn(acc[mi][ni][2 * half], acc[mi][ni][2 * half + 1]);
                }
            }
        }
    }
}

// ---------------------------------------------------------------------------
// bf16 streaming GEMM (abp-style fragments, BK=32, warp tile 32x64).
// C(rows x 128-block) = A(rows x K, fp32) @ W(K x N, fp32), bf16 MMA, fp32 acc.
// EPI: 1 = +bias store; 4 = relu(+bias + di*vm + dz*vr)  (update MLP)
// ---------------------------------------------------------------------------
template <int EPI, typename OutT>
__global__ __launch_bounds__(256) void gemm_bf16s(
    const float* __restrict__ A, int lda, const float* __restrict__ W, int ldb,
    OutT* __restrict__ C, int ldc, const float* __restrict__ bias, int K,
    const int* __restrict__ pin, const int* __restrict__ pout,
    const float* __restrict__ vm, const float* __restrict__ vr)
{
    __shared__ uint2 As[2][2][128][4];   // [p][kq][m][c]
    __shared__ uint2 Bs[2][2][128][4];   // [p][kq][n][c]
    const int row0 = blockIdx.y * 128, col0 = blockIdx.x * 128;
    const int t = threadIdx.x, lane = t & 31, warp = t >> 5;
    const int g = lane >> 2, c = lane & 3;
    const int wm = (warp & 3) * 32;
    const int wn = (warp >> 2) * 64;
    const int lr = t >> 1, ah = t & 1;   // A loader
    const int bn = t & 127, bq = t >> 7; // B loader

    float acc[2][8][4];
    #pragma unroll
    for (int mi = 0; mi < 2; ++mi)
        #pragma unroll
        for (int ni = 0; ni < 8; ++ni)
            #pragma unroll
            for (int j = 0; j < 4; ++j) acc[mi][ni][j] = 0.f;

    float fa[16], wb[16];

    auto gload = [&](int k0) {
        const float* ap = A + (size_t)(row0 + lr) * lda + k0 + 16 * ah;
        #pragma unroll
        for (int j = 0; j < 4; ++j) *(float4*)(fa + 4 * j) = *(const float4*)(ap + 4 * j);
        const float* wp = W + (size_t)(k0 + 16 * bq) * ldb + col0 + bn;
        #pragma unroll
        for (int cc = 0; cc < 4; ++cc) {
            wb[4 * cc + 0] = wp[(size_t)(2 * cc)     * ldb];
            wb[4 * cc + 1] = wp[(size_t)(2 * cc + 1) * ldb];
            wb[4 * cc + 2] = wp[(size_t)(2 * cc + 8) * ldb];
            wb[4 * cc + 3] = wp[(size_t)(2 * cc + 9) * ldb];
        }
    };
    auto sstore = [&](int p) {
        #pragma unroll
        for (int cc = 0; cc < 4; ++cc)
            As[p][ah][lr][cc] =
                make_uint2(pkbf(fa[2 * cc], fa[2 * cc + 1]), pkbf(fa[2 * cc + 8], fa[2 * cc + 9]));
        #pragma unroll
        for (int cc = 0; cc < 4; ++cc)
            Bs[p][bq][bn][cc] =
                make_uint2(pkbf(wb[4 * cc], wb[4 * cc + 1]), pkbf(wb[4 * cc + 2], wb[4 * cc + 3]));
    };
    auto scompute = [&](int p) {
        #pragma unroll
        for (int kq = 0; kq < 2; ++kq) {
            uint32_t af[2][4];
            #pragma unroll
            for (int mi = 0; mi < 2; ++mi) {
                int m = wm + mi * 16;
                uint2 u0 = As[p][kq][m + g][c];
                uint2 u1 = As[p][kq][m + g + 8][c];
                af[mi][0] = u0.x; af[mi][1] = u1.x;
                af[mi][2] = u0.y; af[mi][3] = u1.y;
            }
            uint32_t bf[8][2];
            #pragma unroll
            for (int ni = 0; ni < 8; ++ni) {
                uint2 v = Bs[p][kq][wn + ni * 8 + g][c];
                bf[ni][0] = v.x; bf[ni][1] = v.y;
            }
            #pragma unroll
            for (int mi = 0; mi < 2; ++mi)
                #pragma unroll
                for (int ni = 0; ni < 8; ++ni)
                    mma_bf16(acc[mi][ni], af[mi], bf[ni]);
        }
    };

    gload(0);
    sstore(0);
    __syncthreads();
    int p = 0;
    for (int k0 = 0; k0 < K; k0 += 32) {
        const bool more = (k0 + 32 < K);
        if (more) gload(k0 + 32);
        scompute(p);
        if (more) sstore(p ^ 1);
        __syncthreads();
        p ^= 1;
    }
    #pragma unroll
    for (int mi = 0; mi < 2; ++mi) {
        #pragma unroll
        for (int half = 0; half < 2; ++half) {
            int r = row0 + wm + mi * 16 + g + half * 8;
            float di = 0.f, dz = 0.f;
            if (EPI == 4) {
                di = (float)(pin [r + 1] - pin [r]);
                dz = (float)(pout[r + 1] - pout[r]);
            }
            #pragma unroll
            for (int ni = 0; ni < 8; ++ni) {
                int col = col0 + wn + ni * 8 + 2 * c;
                float v0 = acc[mi][ni][2 * half + 0] + bias[col];
                float v1 = acc[mi][ni][2 * half + 1] + bias[col + 1];
                if (EPI == 4) {
                    v0 += di * vm[col]     + dz * vr[col];
                    v1 += di * vm[col + 1] + dz * vr[col + 1];
                    v0 = fmaxf(v0, 0.f); v1 = fmaxf(v1, 0.f);
                }
                store2(v0, v1, &C[(size_t)r * ldc + col]);
            }
        }
    }
}

// ---------------------------------------------------------------------------
// tf32 tensor-core GEMM, double-buffered smem pipeline.
// ---------------------------------------------------------------------------
template <int BN, int EPI, typename OutT>
__global__ __launch_bounds__(256) void gemm_tf32(
    const float* __restrict__ A, int lda, const float* __restrict__ W, int ldb,
    OutT* __restrict__ C, int ldc, const float* __restrict__ bias, int K)
{
    constexpr int BM = 128, BK = 16;
    constexpr int WN = BN / 4;
    constexpr int NI = WN / 8;
    constexpr int NITB = (BK * BN) / 1024;
    __shared__ uint2    As2[2][2][BM][4];
    __shared__ uint32_t Bs[2][BK][BN + 8];
    const int row0 = blockIdx.y * BM, col0 = blockIdx.x * BN;
    const int t = threadIdx.x, lane = t & 31, warp = t >> 5;
    const int wm = (warp & 1) * 64;
    const int wn = (warp >> 1) * WN;
    const int g = lane >> 2, c = lane & 3;
    const int am = t >> 1, aks = t & 1;

    float acc[4][NI][4];
    #pragma unroll
    for (int mi = 0; mi < 4; ++mi)
        #pragma unroll
        for (int ni = 0; ni < NI; ++ni)
            #pragma unroll
            for (int j = 0; j < 4; ++j) acc[mi][ni][j] = 0.f;

    float4 ra0, ra1, rb[NITB];

    auto gload = [&](int k0) {
        const float* ap = &A[(size_t)(row0 + am) * lda + k0 + aks * 8];
        ra0 = *(const float4*)(ap);
        ra1 = *(const float4*)(ap + 4);
        #pragma unroll
        for (int it = 0; it < NITB; ++it) {
            int kk = t / (BN / 4) + it * (1024 / BN);
            int nq = (t % (BN / 4)) * 4;
            rb[it] = *(const float4*)&W[(size_t)(k0 + kk) * ldb + col0 + nq];
        }
    };
    auto sstore = [&](int p) {
        As2[p][aks][am][0] = make_uint2(f2tf32(ra0.x), f2tf32(ra1.x));
        As2[p][aks][am][1] = make_uint2(f2tf32(ra0.y), f2tf32(ra1.y));
        As2[p][aks][am][2] = make_uint2(f2tf32(ra0.z), f2tf32(ra1.z));
        As2[p][aks][am][3] = make_uint2(f2tf32(ra0.w), f2tf32(ra1.w));
        #pragma unroll
        for (int it = 0; it < NITB; ++it) {
            int kk = t / (BN / 4) + it * (1024 / BN);
            int nq = (t % (BN / 4)) * 4;
            uint32_t* dst = &Bs[p][kk][nq];
            dst[0] = f2tf32(rb[it].x); dst[1] = f2tf32(rb[it].y);
            dst[2] = f2tf32(rb[it].z); dst[3] = f2tf32(rb[it].w);
        }
    };
    auto scompute = [&](int p) {
        #pragma unroll
        for (int ks = 0; ks < 2; ++ks) {
            const int kb = ks * 8;
            uint32_t af[4][4];
            #pragma unroll
            for (int mi = 0; mi < 4; ++mi) {
                int m = wm + mi * 16;
                uint2 u0 = As2[p][ks][m + g][c];
                uint2 u1 = As2[p][ks][m + g + 8][c];
                af[mi][0] = u0.x; af[mi][1] = u1.x;
                af[mi][2] = u0.y; af[mi][3] = u1.y;
            }
            uint32_t bf[NI][2];
            #pragma unroll
            for (int ni = 0; ni < NI; ++ni) {
                int n = wn + ni * 8 + g;
                bf[ni][0] = Bs[p][kb + c][n];
                bf[ni][1] = Bs[p][kb + c + 4][n];
            }
            #pragma unroll
            for (int mi = 0; mi < 4; ++mi)
                #pragma unroll
                for (int ni = 0; ni < NI; ++ni)
                    mma_tf32(acc[mi][ni], af[mi], bf[ni]);
        }
    };

    gload(0);
    sstore(0);
    __syncthreads();
    int p = 0;
    for (int k0 = 0; k0 < K; k0 += BK) {
        const bool more = (k0 + BK < K);
        if (more) gload(k0 + BK);
        scompute(p);
        if (more) sstore(p ^ 1);
        __syncthreads();
        p ^= 1;
    }
    #pragma unroll
    for (int mi = 0; mi < 4; ++mi) {
        #pragma unroll
        for (int ni = 0; ni < NI; ++ni) {
            int row = row0 + wm + mi * 16 + g;
            int col = col0 + wn + ni * 8 + 2 * c;
            #pragma unroll
            for (int half = 0; half < 2; ++half) {
                int r = row + half * 8;
                float v0 = acc[mi][ni][2 * half + 0];
                float v1 = acc[mi][ni][2 * half + 1];
                if (EPI >= 1) { v0 += bias[col]; v1 += bias[col + 1]; }
                if (EPI == 2) { v0 = fmaxf(v0, 0.f); v1 = fmaxf(v1, 0.f); }
                size_t off = (size_t)r * ldc + col;
                if (EPI == 3) { C[off] += v0; C[off + 1] += v1; }
                else          store2(v0, v1, &C[off]);
            }
        }
    }
}

__global__ void pack_w1cb(const float* __restrict__ m1, const float* __restrict__ r1,
                          __nv_bfloat16* __restrict__ w) {
    int i = blockIdx.x * 256 + threadIdx.x;
    if (i >= 1024 * 128) return;
    int n = i >> 7, k = i & 127;
    float v;
    if (n < 256)      v = m1[k * 256 + n];
    else if (n < 512) v = m1[(128 + k) * 256 + (n - 256)];
    else if (n < 768) v = r1[k * 256 + (n - 512)];
    else              v = r1[(128 + k) * 256 + (n - 768)];
    w[i] = __float2bfloat16(v);
}
__global__ void pack_w2cat(const float* __restrict__ m2, const float* __restrict__ r2,
                           float* __restrict__ w) {
    int i = blockIdx.x * 256 + threadIdx.x;
    if (i >= 512 * 128) return;
    int k = i >> 7, j = i & 127;
    w[i] = (k < 256) ? m2[k * 128 + j] : r2[(k - 256) * 128 + j];
}
__global__ void pack_u1bot(const float* __restrict__ u1, float* __restrict__ W1u) {
    int i = blockIdx.x * 256 + threadIdx.x;
    if (i >= 128 * 256) return;
    W1u[512 * 256 + i] = u1[128 * 256 + i];
}
__global__ void vmvr_kernel(const float* __restrict__ u1, const float* __restrict__ mb2,
                            const float* __restrict__ rb2, float* __restrict__ vm,
                            float* __restrict__ vr) {
    int j = threadIdx.x;
    float sm = 0.f, sr = 0.f;
    for (int k = 0; k < 128; ++k) {
        float u = u1[k * 256 + j];
        sm += mb2[k] * u;
        sr += rb2[k] * u;
    }
    vm[j] = sm; vr[j] = sr;
}
__global__ void pack_wecat(const float* __restrict__ m1, const float* __restrict__ r1,
                           const float* __restrict__ mb1, const float* __restrict__ rb1,
                           float* __restrict__ w, float* __restrict__ bcat) {
    int i = blockIdx.x * 256 + threadIdx.x;
    if (i < 64 * 512) {
        int k = i >> 9, j = i & 511;
        w[i] = (j < 256) ? m1[(256 + k) * 256 + j] : r1[(256 + k) * 256 + (j - 256)];
    }
    if (i < 512) bcat[i] = (i < 256) ? mb1[i] : rb1[i - 256];
}

__global__ void deg_count(const int* __restrict__ fr, const int* __restrict__ to,
                          int* din, int* dout, int E) {
    int e = blockIdx.x * 256 + threadIdx.x;
    if (e < E) { atomicAdd(&din[to[e]], 1); atomicAdd(&dout[fr[e]], 1); }
}
__global__ void exscan_kernel(const int* __restrict__ in, int* __restrict__ out, int n) {
    __shared__ int buf[1024];
    __shared__ int carry_s;
    int t = threadIdx.x;
    if (t == 0) carry_s = 0;
    __syncthreads();
    for (int base = 0; base < n; base += 1024) {
        int i = base + t;
        int v = (i < n) ? in[i] : 0;
        buf[t] = v;
        __syncthreads();
        for (int d = 1; d < 1024; d <<= 1) {
            int x = (t >= d) ? buf[t - d] : 0;
            __syncthreads();
            buf[t] += x;
            __syncthreads();
        }
        if (i < n) out[i] = carry_s + buf[t] - v;
        int tot = buf[1023];
        __syncthreads();
        if (t == 0) carry_s += tot;
        __syncthreads();
    }
    if (t == 0) out[n] = carry_s;
}
__global__ void csr_fill(const int* __restrict__ fr, const int* __restrict__ to,
                         int* cin, int* cout, int* iin, int* iout, int E) {
    int e = blockIdx.x * 256 + threadIdx.x;
    if (e < E) {
        int s  = atomicAdd(&cin [to[e]], 1); iin [s]  = e;
        int s2 = atomicAdd(&cout[fr[e]], 1); iout[s2] = e;
    }
}

__global__ __launch_bounds__(256) void permute_eenc(
    const float* __restrict__ eenc, const int* __restrict__ idx,
    const int* __restrict__ endp, float* __restrict__ out,
    int* __restrict__ ocsr, int E)
{
    int j = blockIdx.x * 8 + (threadIdx.x >> 5);
    if (j >= E) return;
    int lane = threadIdx.x & 31;
    int e = idx[j];
    if (lane == 0) ocsr[j] = endp[e];
    const float2* s2 = (const float2*)(eenc + (size_t)e * 64);
    float2* d2 = (float2*)(out + (size_t)j * 64);
    d2[lane] = s2[lane];
}

__global__ __launch_bounds__(256) void agg_kernel(
    const int* __restrict__ ptr, const int* __restrict__ ocsr,
    const __nv_bfloat162* __restrict__ AB, int aoff, int boff,
    const __nv_bfloat162* __restrict__ ecsr,
    float* __restrict__ catA, int ooff, int Nn)
{
    int n = (blockIdx.x * blockDim.x + threadIdx.x) >> 5;
    int lane = threadIdx.x & 31;
    if (n >= Nn) return;
    float bv[8], acc[8];
    const __nv_bfloat162* bp = AB + (size_t)n * 512 + boff;
    #pragma unroll
    for (int k = 0; k < 4; ++k) {
        float2 b2 = __bfloat1622float2(bp[lane + 32 * k]);
        bv[2 * k] = b2.x; bv[2 * k + 1] = b2.y;
        acc[2 * k] = 0.f; acc[2 * k + 1] = 0.f;
    }
    int s = ptr[n], e1 = ptr[n + 1];
    for (int j = s; j < e1; ++j) {
        int o = ocsr[j];
        const __nv_bfloat162* ap = AB + (size_t)o * 512 + aoff;
        const __nv_bfloat162* ep = ecsr + (size_t)j * 128;
        #pragma unroll
        for (int k = 0; k < 4; ++k) {
            float2 a2 = __bfloat1622float2(ap[lane + 32 * k]);
            float2 e2 = __bfloat1622float2(ep[lane + 32 * k]);
            acc[2 * k]     += fmaxf(a2.x + e2.x + bv[2 * k],     0.f);
            acc[2 * k + 1] += fmaxf(a2.y + e2.y + bv[2 * k + 1], 0.f);
        }
    }
    float2* op = (float2*)(catA + (size_t)n * 640 + ooff);
    #pragma unroll
    for (int k = 0; k < 4; ++k) op[lane + 32 * k] = make_float2(acc[2 * k], acc[2 * k + 1]);
}

__global__ void copy_h_kernel(const float* __restrict__ h, float* __restrict__ catA) {
    int n = blockIdx.x, t = threadIdx.x;
    catA[(size_t)n * 640 + 512 + t] = h[(size_t)n * 128 + t];
}

__global__ void build_sizes(const int* __restrict__ qs, const int* __restrict__ cs,
                            int* __restrict__ sizes, int B2) {
    int i = blockIdx.x * 256 + threadIdx.x;
    if (i < B2) sizes[i] = (i & 1) ? cs[i >> 1] : qs[i >> 1];
}
__global__ void scatter_kernel(const float* __restrict__ h, const int* __restrict__ gidx,
                               const int* __restrict__ starts, float* __restrict__ st) {
    int n = blockIdx.x, t = threadIdx.x;
    int g = gidx[n];
    int pos = n - starts[g];
    st[((size_t)g * 128 + pos) * 128 + t] = h[(size_t)n * 128 + t];
}
__global__ void mask_kernel(float* __restrict__ tt, const int* __restrict__ qs,
                            const int* __restrict__ cs) {
    int r = blockIdx.x, j = threadIdx.x;
    int b = r >> 8, side = (r >> 7) & 1, pos = r & 127;
    int sz = side ? cs[b] : qs[b];
    if (pos >= sz) tt[(size_t)r * 128 + j] = 0.f;
}

__global__ __launch_bounds__(256) void pair_gemm_kernel(const float* __restrict__ tt,
                                                        float* __restrict__ la) {
    int b = blockIdx.x;
    const float* Aq = tt + (size_t)(2 * b)     * 16384;
    const float* Ac = tt + (size_t)(2 * b + 1) * 16384;
    __shared__ float As[16][132], Bs[16][132];
    int t = threadIdx.x, tx = t & 15, ty = t >> 4;
    float acc[8][8];
    #pragma unroll
    for (int i = 0; i < 8; ++i)
        #pragma unroll
        for (int j = 0; j < 8; ++j) acc[i][j] = 0.f;
    for (int k0 = 0; k0 < 128; k0 += 16) {
        #pragma unroll
        for (int it = 0; it < 2; ++it) {
            int m = (t >> 2) + it * 64, kq = (t & 3) * 4;
            float4 v = *(const float4*)&Aq[m * 128 + k0 + kq];
            As[kq][m] = v.x; As[kq + 1][m] = v.y; As[kq + 2][m] = v.z; As[kq + 3][m] = v.w;
            float4 w = *(const float4*)&Ac[m * 128 + k0 + kq];
            Bs[kq][m] = w.x; Bs[kq + 1][m] = w.y; Bs[kq + 2][m] = w.z; Bs[kq + 3][m] = w.w;
        }
        __syncthreads();
        #pragma unroll
        for (int k = 0; k < 16; ++k) {
            float a[8], bv[8];
            *(float4*)(a)      = *(const float4*)&As[k][ty * 8];
            *(float4*)(a + 4)  = *(const float4*)&As[k][ty * 8 + 4];
            *(float4*)(bv)     = *(const float4*)&Bs[k][tx * 8];
            *(float4*)(bv + 4) = *(const float4*)&Bs[k][tx * 8 + 4];
            #pragma unroll
            for (int i = 0; i < 8; ++i)
                #pragma unroll
                for (int j = 0; j < 8; ++j) acc[i][j] += a[i] * bv[j];
        }
        __syncthreads();
    }
    float* dst = la + (size_t)b * 16384;
    #pragma unroll
    for (int i = 0; i < 8; ++i)
        #pragma unroll
        for (int j = 0; j < 8; ++j)
            dst[(ty * 8 + i) * 128 + tx * 8 + j] = acc[i][j] * 10.0f;
}

__global__ __launch_bounds__(256) void sinkhorn_kernel(float* __restrict__ la_g,
                                                       const int* __restrict__ qs,
                                                       const int* __restrict__ cs) {
    extern __shared__ float P[];
    const int b = blockIdx.x;
    const int R = qs[b], C = cs[b];
    const float wR = (float)(128 - R), wC = (float)(128 - C);
    const int RT = (R < 128) ? R + 1 : 128;
    const int CT = (C < 128) ? C + 1 : 128;
    float* src = la_g + (size_t)b * 16384;
    const int t = threadIdx.x;
    for (int i = t; i < RT * CT; i += 256) {
        int q = i / CT, c = i % CT;
        P[q * 131 + c] = (q < R && c < C) ? src[q * 128 + c] : 0.f;
    }
    __syncthreads();
    const int warp = t >> 5, lane = t & 31;
    for (int iter = 0; iter < 20; ++iter) {
        for (int q = warp; q < RT; q += 8) {
            float m = -1e30f;
            for (int c = lane; c < CT; c += 32) m = fmaxf(m, P[q * 131 + c]);
            m = warp_max(m);
            float s = 0.f;
            for (int c = lane; c < CT; c += 32) {
                float w = (c == C) ? wC : 1.f;
                s += w * __expf(P[q * 131 + c] - m);
            }
            s = warp_sum(s);
            float lse = m + __logf(s);
            for (int c = lane; c < CT; c += 32) P[q * 131 + c] -= lse;
        }
        __syncthreads();
        for (int c = warp; c < CT; c += 8) {
            float m = -1e30f;
            for (int q = lane; q < RT; q += 32) m = fmaxf(m, P[q * 131 + c]);
            m = warp_max(m);
            float s = 0.f;
            for (int q = lane; q < RT; q += 32) {
                float w = (q == R) ? wR : 1.f;
                s += w * __expf(P[q * 131 + c] - m);
            }
            s = warp_sum(s);
            float lse = m + __logf(s);
            for (int q = lane; q < RT; q += 32) P[q * 131 + c] -= lse;
        }
        __syncthreads();
    }
    for (int i = t; i < 16384; i += 256) {
        int q = i >> 7, c = i & 127;
        int qe = (q < R) ? q : R;
        int ce = (c < C) ? c : C;
        src[i] = __expf(P[qe * 131 + ce]);
    }
}

__global__ __launch_bounds__(256) void score_kernel(const float* __restrict__ plan,
                                                    const float* __restrict__ stacked,
                                                    float* __restrict__ out) {
    int b = blockIdx.x;
    const float* P  = plan    + (size_t)b * 16384;
    const float* Q  = stacked + (size_t)(2 * b)     * 16384;
    const float* Cm = stacked + (size_t)(2 * b + 1) * 16384;
    __shared__ float As[16][132], Bs[16][132];
    int t = threadIdx.x, tx = t & 15, ty = t >> 4;
    float acc[8][8];
    #pragma unroll
    for (int i = 0; i < 8; ++i)
        #pragma unroll
        for (int j = 0; j < 8; ++j) acc[i][j] = 0.f;
    for (int k0 = 0; k0 < 128; k0 += 16) {
        #pragma unroll
        for (int it = 0; it < 2; ++it) {
            int m = (t >> 2) + it * 64, kq = (t & 3) * 4;
            float4 v = *(const float4*)&P[m * 128 + k0 + kq];
            As[kq][m] = v.x; As[kq + 1][m] = v.y; As[kq + 2][m] = v.z; As[kq + 3][m] = v.w;
        }
        #pragma unroll
        for (int it = 0; it < 2; ++it) {
            int kk = (t >> 5) + it * 8, nq = (t & 31) * 4;
            *(float4*)&Bs[kk][nq] = *(const float4*)&Cm[(k0 + kk) * 128 + nq];
        }
        __syncthreads();
        #pragma unroll
        for (int k = 0; k < 16; ++k) {
            float a[8], bv[8];
            *(float4*)(a)      = *(const float4*)&As[k][ty * 8];
            *(float4*)(a + 4)  = *(const float4*)&As[k][ty * 8 + 4];
            *(float4*)(bv)     = *(const float4*)&Bs[k][tx * 8];
            *(float4*)(bv + 4) = *(const float4*)&Bs[k][tx * 8 + 4];
            #pragma unroll
            for (int i = 0; i < 8; ++i)
                #pragma unroll
                for (int j = 0; j < 8; ++j) acc[i][j] += a[i] * bv[j];
        }
        __syncthreads();
    }
    float s = 0.f;
    #pragma unroll
    for (int i = 0; i < 8; ++i)
        #pragma unroll
        for (int j = 0; j < 8; ++j)
            s += fmaxf(Q[(ty * 8 + i) * 128 + tx * 8 + j] - acc[i][j], 0.f);
    s = warp_sum(s);
    __shared__ float red[8];
    if ((t & 31) == 0) red[t >> 5] = s;
    __syncthreads();
    if (t == 0) {
        float tot = 0.f;
        #pragma unroll
        for (int i = 0; i < 8; ++i) tot += red[i];
        out[b] = -tot;
    }
}

template <typename T>
static T* sym(const void* s) { void* p = nullptr; cudaGetSymbolAddress(&p, s); return (T*)p; }

extern "C" void kernel_launch(void* const* d_in, const int* in_sizes, int n_in,
                              void* d_out, int out_size) {
    const float* nf  = (const float*)d_in[0];
    const float* ef  = (const float*)d_in[1];
    const float* enW = (const float*)d_in[2];  const float* enB = (const float*)d_in[3];
    const float* eeW = (const float*)d_in[4];  const float* eeB = (const float*)d_in[5];
    const float* m1  = (const float*)d_in[6];  const float* mb1 = (const float*)d_in[7];
    const float* m2  = (const float*)d_in[8];  const float* mb2 = (const float*)d_in[9];
    const float* r1  = (const float*)d_in[10]; const float* rb1 = (const float*)d_in[11];
    const float* r2  = (const float*)d_in[12]; const float* rb2 = (const float*)d_in[13];
    const float* u1  = (const float*)d_in[14]; const float* ub1 = (const float*)d_in[15];
    const float* u2  = (const float*)d_in[16]; const float* ub2 = (const float*)d_in[17];
    const float* f1  = (const float*)d_in[18]; const float* f1b = (const float*)d_in[19];
    const float* f2  = (const float*)d_in[20]; const float* f2b = (const float*)d_in[21];
    const int* fr  = (const int*)d_in[22];
    const int* to  = (const int*)d_in[23];
    const int* gix = (const int*)d_in[24];
    const int* qs  = (const int*)d_in[25];
    const int* cs  = (const int*)d_in[26];
    const int E  = in_sizes[22];
    const int N  = in_sizes[24];
    const int B  = in_sizes[25];
    const int B2 = 2 * B;
    float* out = (float*)d_out;

    float* h    = sym<float>(g_h);    float* eenc = sym<float>(g_eenc);
    float* eP   = sym<float>(g_eP);
    __nv_bfloat16* ABh = sym<__nv_bfloat16>(g_ABh);
    __nv_bfloat16* eMc = sym<__nv_bfloat16>(g_eMc);
    __nv_bfloat16* eRc = sym<__nv_bfloat16>(g_eRc);
    __nv_bfloat16* W1cb = sym<__nv_bfloat16>(g_W1cb);
    float* catA = sym<float>(g_catA);
    float* hid  = sym<float>(g_hid);  float* tt   = sym<float>(g_t);
    float* stk  = sym<float>(g_stk);  float* la   = sym<float>(g_la);
    float* W2c  = sym<float>(g_W2cat);
    float* W1u  = sym<float>(g_W1u);
    float* vm   = sym<float>(g_vm);   float* vr   = sym<float>(g_vr);
    float* Wec  = sym<float>(g_Wecat); float* bec = sym<float>(g_becat);
    int* sizes = sym<int>(g_sizes); int* starts = sym<int>(g_starts);
    int* din = sym<int>(g_din);   int* dout = sym<int>(g_dout);
    int* pin = sym<int>(g_pin);   int* pout = sym<int>(g_pout);
    int* cin = sym<int>(g_cin);   int* cout = sym<int>(g_cout);
    int* iin = sym<int>(g_iin);   int* iout = sym<int>(g_iout);
    int* oin = sym<int>(g_oin);   int* oout = sym<int>(g_oout);
    float* ePa = eP;
    float* ePb = eP + (size_t)EMAX * 64;

    const int ABP_SMEM = 2 * 4096 * 8;  // 64 KB

    static bool attr_set = false;
    if (!attr_set) {
        cudaFuncSetAttribute(sinkhorn_kernel,
                             cudaFuncAttributeMaxDynamicSharedMemorySize, 129 * 131 * 4);
        cudaFuncSetAttribute(abp_fused,
                             cudaFuncAttributeMaxDynamicSharedMemorySize, ABP_SMEM);
        attr_set = true;
    }

    // ---- launches 1-6; #4 (= ncu capture) is abp_fused ----
    gemm_tf32<128, 1, float><<<dim3(1, N / 128), 256>>>(nf, 32, enW, 128, h, 128, enB, 32);
    pack_w1cb<<<(1024 * 128 + 255) / 256, 256>>>(m1, r1, W1cb);
    pack_wecat<<<(64 * 512 + 255) / 256, 256>>>(m1, r1, mb1, rb1, Wec, bec);
    abp_fused<<<N / 128, 256, ABP_SMEM>>>(h, W1cb, ABh);
    pack_w2cat<<<(512 * 128 + 255) / 256, 256>>>(m2, r2, W2c);
    gemm_tf32<64, 1, float><<<dim3(1, E / 128), 256>>>(ef, 16, eeW, 64, eenc, 64, eeB, 16);

    // ---- fused-update precompute: W1u = [W2c@u1_top ; u1_bot], vm, vr ----
    gemm_tf32<128, 0, float><<<dim3(2, 4), 256>>>(W2c, 128, u1, 256, W1u, 256, nullptr, 128);
    pack_u1bot<<<(128 * 256 + 255) / 256, 256>>>(u1, W1u);
    vmvr_kernel<<<1, 256>>>(u1, mb2, rb2, vm, vr);

    // ---- graph structure ----
    zero_i<<<(N + 255) / 256, 256>>>(din, N);
    zero_i<<<(N + 255) / 256, 256>>>(dout, N);
    build_sizes<<<(B2 + 255) / 256, 256>>>(qs, cs, sizes, B2);
    exscan_kernel<<<1, 1024>>>(sizes, starts, B2);
    deg_count<<<(E + 255) / 256, 256>>>(fr, to, din, dout, E);
    exscan_kernel<<<1, 1024>>>(din, pin, N);
    exscan_kernel<<<1, 1024>>>(dout, pout, N);
    copy_i<<<(N + 255) / 256, 256>>>(pin, cin, N);
    copy_i<<<(N + 255) / 256, 256>>>(pout, cout, N);
    csr_fill<<<(E + 255) / 256, 256>>>(fr, to, cin, cout, iin, iout, E);

    // ---- edge constants: permute eenc, bf16s GEMM directly to bf16 CSR ----
    permute_eenc<<<(E + 7) / 8, 256>>>(eenc, iin,  fr, ePa, oin,  E);
    permute_eenc<<<(E + 7) / 8, 256>>>(eenc, iout, to, ePb, oout, E);
    gemm_bf16s<1, __nv_bfloat16><<<dim3(2, E / 128), 256>>>(
        ePa, 64, Wec, 512, eMc, 256, bec, 64, nullptr, nullptr, nullptr, nullptr);
    gemm_bf16s<1, __nv_bfloat16><<<dim3(2, E / 128), 256>>>(
        ePb, 64, Wec + 256, 512, eRc, 256, bec + 256, 64, nullptr, nullptr, nullptr, nullptr);

    // ---- propagation rounds (round 0's ABp already done above) ----
    for (int r = 0; r < 5; ++r) {
        if (r > 0)
            abp_fused<<<N / 128, 256, ABP_SMEM>>>(h, W1cb, ABh);
        agg_kernel<<<(N + 7) / 8, 256>>>(pin,  oin,  (const __nv_bfloat162*)ABh, 0,   128,
                                         (const __nv_bfloat162*)eMc, catA, 0,   N);
        agg_kernel<<<(N + 7) / 8, 256>>>(pout, oout, (const __nv_bfloat162*)ABh, 256, 384,
                                         (const __nv_bfloat162*)eRc, catA, 256, N);
        copy_h_kernel<<<N, 128>>>(h, catA);
        gemm_bf16s<4, float><<<dim3(2, N / 128), 256>>>(
            catA, 640, W1u, 256, hid, 256, ub1, 640, pin, pout, vm, vr);
        gemm_tf32<128, 3, float><<<dim3(1, N / 128), 256>>>(hid, 256, u2, 128, h, 128, ub2, 256);
    }

    // ---- stack + transform ----
    zero_f<<<2048, 256>>>(stk, (size_t)B2 * 16384);
    scatter_kernel<<<N, 128>>>(h, gix, starts, stk);
    gemm_tf32<128, 2, float><<<dim3(1, B2 * 128 / 128), 256>>>(stk, 128, f1, 128, hid, 128, f1b, 128);
    gemm_tf32<128, 1, float><<<dim3(1, B2 * 128 / 128), 256>>>(hid, 128, f2, 128, tt, 128, f2b, 128);
    mask_kernel<<<B2 * 128, 128>>>(tt, qs, cs);

    // ---- sinkhorn + score ----
    pair_gemm_kernel<<<B, 256>>>(tt, la);
    sinkhorn_kernel<<<B, 256, 129 * 131 * 4>>>(la, qs, cs);
    score_kernel<<<B, 256>>>(la, stk, out);
}

// round 16
// speedup vs baseline: 1.1099x; 1.0351x over previous
#include <cuda_runtime.h>
#include <cuda_bf16.h>
#include <cstdint>
#include <cstddef>

#define NMAX 98304
#define EMAX 786432
#define BMAX 512

__device__ float g_h   [(size_t)NMAX * 128];
__device__ float g_eenc[(size_t)EMAX * 64];
__device__ float g_eP  [(size_t)EMAX * 128];
__device__ __nv_bfloat16 g_ABh [(size_t)NMAX * 1024];
__device__ __nv_bfloat16 g_eMc [(size_t)EMAX * 256];
__device__ __nv_bfloat16 g_eRc [(size_t)EMAX * 256];
__device__ __nv_bfloat16 g_W1cb[1024 * 128];
__device__ float g_catA[(size_t)NMAX * 640];
__device__ float g_hid [(size_t)NMAX * 256];
__device__ float g_t   [(size_t)BMAX * 2 * 128 * 128];
__device__ float g_stk [(size_t)BMAX * 2 * 128 * 128];
__device__ float g_la  [(size_t)BMAX * 128 * 128];
__device__ float g_W2cat[512 * 128];
__device__ float g_W1u [640 * 256];
__device__ float g_vm  [256];
__device__ float g_vr  [256];
__device__ float g_Wecat[64 * 512];
__device__ float g_becat[512];
__device__ int   g_sizes [2 * BMAX];
__device__ int   g_starts[2 * BMAX + 1];
__device__ int   g_din [NMAX];
__device__ int   g_dout[NMAX];
__device__ int   g_pin [NMAX + 1];
__device__ int   g_pout[NMAX + 1];
__device__ int   g_cin [NMAX];
__device__ int   g_cout[NMAX];
__device__ int   g_iin [EMAX];
__device__ int   g_iout[EMAX];
__device__ int   g_oin [EMAX];
__device__ int   g_oout[EMAX];

__device__ __forceinline__ float warp_max(float v) {
    #pragma unroll
    for (int o = 16; o; o >>= 1) v = fmaxf(v, __shfl_xor_sync(0xffffffffu, v, o));
    return v;
}
__device__ __forceinline__ float warp_sum(float v) {
    #pragma unroll
    for (int o = 16; o; o >>= 1) v += __shfl_xor_sync(0xffffffffu, v, o);
    return v;
}
__device__ __forceinline__ uint32_t f2tf32(float x) {
    uint32_t r;
    asm("cvt.rna.tf32.f32 %0, %1;" : "=r"(r) : "f"(x));
    return r;
}
__device__ __forceinline__ uint32_t pkbf(float x, float y) {
    __nv_bfloat162 h = __floats2bfloat162_rn(x, y);
    return *(uint32_t*)&h;
}
__device__ __forceinline__ void mma_tf32(float* d, const uint32_t* a, const uint32_t* b) {
    asm volatile(
        "mma.sync.aligned.m16n8k8.row.col.f32.tf32.tf32.f32 "
        "{%0,%1,%2,%3}, {%4,%5,%6,%7}, {%8,%9}, {%0,%1,%2,%3};"
        : "+f"(d[0]), "+f"(d[1]), "+f"(d[2]), "+f"(d[3])
        : "r"(a[0]), "r"(a[1]), "r"(a[2]), "r"(a[3]), "r"(b[0]), "r"(b[1]));
}
__device__ __forceinline__ void mma_bf16(float* d, const uint32_t* a, const uint32_t* b) {
    asm volatile(
        "mma.sync.aligned.m16n8k16.row.col.f32.bf16.bf16.f32 "
        "{%0,%1,%2,%3}, {%4,%5,%6,%7}, {%8,%9}, {%0,%1,%2,%3};"
        : "+f"(d[0]), "+f"(d[1]), "+f"(d[2]), "+f"(d[3])
        : "r"(a[0]), "r"(a[1]), "r"(a[2]), "r"(a[3]), "r"(b[0]), "r"(b[1]));
}
__device__ __forceinline__ void store2(float v0, float v1, float* p) {
    p[0] = v0; p[1] = v1;
}
__device__ __forceinline__ void store2(float v0, float v1, __nv_bfloat16* p) {
    *(__nv_bfloat162*)p = __floats2bfloat162_rn(v0, v1);
}

__global__ void zero_f(float* p, size_t n) {
    for (size_t i = (size_t)blockIdx.x * 256 + threadIdx.x; i < n;
         i += (size_t)gridDim.x * 256) p[i] = 0.f;
}
__global__ void zero_i(int* p, int n) {
    int i = blockIdx.x * 256 + threadIdx.x;
    if (i < n) p[i] = 0;
}
__global__ void copy_i(const int* a, int* b, int n) {
    int i = blockIdx.x * 256 + threadIdx.x;
    if (i < n) b[i] = a[i];
}

// ---------------------------------------------------------------------------
// Fused ABp GEMM, conflict-free stride-4 fragment layout.
// ---------------------------------------------------------------------------
__global__ __launch_bounds__(256, 2) void abp_fused(
    const float* __restrict__ h, const __nv_bfloat16* __restrict__ W1cb,
    __nv_bfloat16* __restrict__ ABh)
{
    extern __shared__ uint2 sm[];
    uint2* As = sm;
    uint2* Bs = sm + 4096;
    const int t = threadIdx.x, lane = t & 31, warp = t >> 5;
    const int row0 = blockIdx.x * 128;
    const int g = lane >> 2, c = lane & 3;
    const int wm = (warp & 3) * 32;
    const int wn = (warp >> 2) * 64;
    const int lr = t >> 1, ah = t & 1;

    {
        const float* hp = h + (size_t)(row0 + lr) * 128 + 64 * ah;
        #pragma unroll
        for (int kq = 0; kq < 4; ++kq) {
            float f[16];
            #pragma unroll
            for (int j = 0; j < 4; ++j) *(float4*)(f + 4 * j) = *(const float4*)(hp + 16 * kq + 4 * j);
            int kc = 4 * ah + kq;
            #pragma unroll
            for (int cc = 0; cc < 4; ++cc)
                As[kc * 512 + lr * 4 + cc] =
                    make_uint2(pkbf(f[2 * cc], f[2 * cc + 1]), pkbf(f[2 * cc + 8], f[2 * cc + 9]));
        }
    }

    for (int nc = 0; nc < 8; ++nc) {
        __syncthreads();
        {
            const uint32_t* wp = (const uint32_t*)(W1cb + (size_t)(nc * 128 + lr) * 128) + 32 * ah;
            uint32_t r[32];
            #pragma unroll
            for (int j = 0; j < 8; ++j) *(uint4*)(r + 4 * j) = *(const uint4*)(wp + 4 * j);
            #pragma unroll
            for (int kq = 0; kq < 4; ++kq) {
                int kc = 4 * ah + kq;
                #pragma unroll
                for (int cc = 0; cc < 4; ++cc)
                    Bs[kc * 512 + lr * 4 + cc] = make_uint2(r[8 * kq + cc], r[8 * kq + cc + 4]);
            }
        }
        __syncthreads();

        float acc[2][8][4];
        #pragma unroll
        for (int mi = 0; mi < 2; ++mi)
            #pragma unroll
            for (int ni = 0; ni < 8; ++ni)
                #pragma unroll
                for (int j = 0; j < 4; ++j) acc[mi][ni][j] = 0.f;

        #pragma unroll
        for (int kc = 0; kc < 8; ++kc) {
            uint32_t af[2][4];
            #pragma unroll
            for (int mi = 0; mi < 2; ++mi) {
                int m = wm + mi * 16;
                uint2 u0 = As[kc * 512 + (m + g) * 4 + c];
                uint2 u1 = As[kc * 512 + (m + g + 8) * 4 + c];
                af[mi][0] = u0.x; af[mi][1] = u1.x;
                af[mi][2] = u0.y; af[mi][3] = u1.y;
            }
            uint32_t bf[8][2];
            #pragma unroll
            for (int ni = 0; ni < 8; ++ni) {
                uint2 v = Bs[kc * 512 + (wn + ni * 8 + g) * 4 + c];
                bf[ni][0] = v.x; bf[ni][1] = v.y;
            }
            #pragma unroll
            for (int mi = 0; mi < 2; ++mi)
                #pragma unroll
                for (int ni = 0; ni < 8; ++ni)
                    mma_bf16(acc[mi][ni], af[mi], bf[ni]);
        }

        #pragma unroll
        for (int mi = 0; mi < 2; ++mi) {
            #pragma unroll
            for (int ni = 0; ni < 8; ++ni) {
                int col = nc * 128 + wn + ni * 8 + 2 * c;
                #pragma unroll
                for (int half = 0; half < 2; ++half) {
                    int row = row0 + wm + mi * 16 + g + half * 8;
                    *(__nv_bfloat162*)(ABh + (size_t)row * 1024 + col) =
                        __floats2bfloat162_rn(acc[mi][ni][2 * half], acc[mi][ni][2 * half + 1]);
                }
            }
        }
    }
}

// ---------------------------------------------------------------------------
// bf16 streaming GEMM (abp-style fragments, BK=32, warp tile 32x64).
// EPI: 1=+bias store; 2=relu(+bias); 3=C+= v+bias; 4=relu(+bias+di*vm+dz*vr)
// ---------------------------------------------------------------------------
template <int EPI, typename OutT>
__global__ __launch_bounds__(256) void gemm_bf16s(
    const float* __restrict__ A, int lda, const float* __restrict__ W, int ldb,
    OutT* __restrict__ C, int ldc, const float* __restrict__ bias, int K,
    const int* __restrict__ pin, const int* __restrict__ pout,
    const float* __restrict__ vm, const float* __restrict__ vr)
{
    __shared__ uint2 As[2][2][128][4];
    __shared__ uint2 Bs[2][2][128][4];
    const int row0 = blockIdx.y * 128, col0 = blockIdx.x * 128;
    const int t = threadIdx.x, lane = t & 31, warp = t >> 5;
    const int g = lane >> 2, c = lane & 3;
    const int wm = (warp & 3) * 32;
    const int wn = (warp >> 2) * 64;
    const int lr = t >> 1, ah = t & 1;
    const int bn = t & 127, bq = t >> 7;

    float acc[2][8][4];
    #pragma unroll
    for (int mi = 0; mi < 2; ++mi)
        #pragma unroll
        for (int ni = 0; ni < 8; ++ni)
            #pragma unroll
            for (int j = 0; j < 4; ++j) acc[mi][ni][j] = 0.f;

    float fa[16], wb[16];

    auto gload = [&](int k0) {
        const float* ap = A + (size_t)(row0 + lr) * lda + k0 + 16 * ah;
        #pragma unroll
        for (int j = 0; j < 4; ++j) *(float4*)(fa + 4 * j) = *(const float4*)(ap + 4 * j);
        const float* wp = W + (size_t)(k0 + 16 * bq) * ldb + col0 + bn;
        #pragma unroll
        for (int cc = 0; cc < 4; ++cc) {
            wb[4 * cc + 0] = wp[(size_t)(2 * cc)     * ldb];
            wb[4 * cc + 1] = wp[(size_t)(2 * cc + 1) * ldb];
            wb[4 * cc + 2] = wp[(size_t)(2 * cc + 8) * ldb];
            wb[4 * cc + 3] = wp[(size_t)(2 * cc + 9) * ldb];
        }
    };
    auto sstore = [&](int p) {
        #pragma unroll
        for (int cc = 0; cc < 4; ++cc)
            As[p][ah][lr][cc] =
                make_uint2(pkbf(fa[2 * cc], fa[2 * cc + 1]), pkbf(fa[2 * cc + 8], fa[2 * cc + 9]));
        #pragma unroll
        for (int cc = 0; cc < 4; ++cc)
            Bs[p][bq][bn][cc] =
                make_uint2(pkbf(wb[4 * cc], wb[4 * cc + 1]), pkbf(wb[4 * cc + 2], wb[4 * cc + 3]));
    };
    auto scompute = [&](int p) {
        #pragma unroll
        for (int kq = 0; kq < 2; ++kq) {
            uint32_t af[2][4];
            #pragma unroll
            for (int mi = 0; mi < 2; ++mi) {
                int m = wm + mi * 16;
                uint2 u0 = As[p][kq][m + g][c];
                uint2 u1 = As[p][kq][m + g + 8][c];
                af[mi][0] = u0.x; af[mi][1] = u1.x;
                af[mi][2] = u0.y; af[mi][3] = u1.y;
            }
            uint32_t bf[8][2];
            #pragma unroll
            for (int ni = 0; ni < 8; ++ni) {
                uint2 v = Bs[p][kq][wn + ni * 8 + g][c];
                bf[ni][0] = v.x; bf[ni][1] = v.y;
            }
            #pragma unroll
            for (int mi = 0; mi < 2; ++mi)
                #pragma unroll
                for (int ni = 0; ni < 8; ++ni)
                    mma_bf16(acc[mi][ni], af[mi], bf[ni]);
        }
    };

    gload(0);
    sstore(0);
    __syncthreads();
    int p = 0;
    for (int k0 = 0; k0 < K; k0 += 32) {
        const bool more = (k0 + 32 < K);
        if (more) gload(k0 + 32);
        scompute(p);
        if (more) sstore(p ^ 1);
        __syncthreads();
        p ^= 1;
    }
    #pragma unroll
    for (int mi = 0; mi < 2; ++mi) {
        #pragma unroll
        for (int half = 0; half < 2; ++half) {
            int r = row0 + wm + mi * 16 + g + half * 8;
            float di = 0.f, dz = 0.f;
            if (EPI == 4) {
                di = (float)(pin [r + 1] - pin [r]);
                dz = (float)(pout[r + 1] - pout[r]);
            }
            #pragma unroll
            for (int ni = 0; ni < 8; ++ni) {
                int col = col0 + wn + ni * 8 + 2 * c;
                float v0 = acc[mi][ni][2 * half + 0] + bias[col];
                float v1 = acc[mi][ni][2 * half + 1] + bias[col + 1];
                size_t off = (size_t)r * ldc + col;
                if (EPI == 4) {
                    v0 += di * vm[col]     + dz * vr[col];
                    v1 += di * vm[col + 1] + dz * vr[col + 1];
                    store2(fmaxf(v0, 0.f), fmaxf(v1, 0.f), &C[off]);
                } else if (EPI == 2) {
                    store2(fmaxf(v0, 0.f), fmaxf(v1, 0.f), &C[off]);
                } else if (EPI == 3) {
                    C[off] += v0; C[off + 1] += v1;
                } else {
                    store2(v0, v1, &C[off]);
                }
            }
        }
    }
}

// ---------------------------------------------------------------------------
// tf32 tensor-core GEMM, double-buffered smem pipeline.
// ---------------------------------------------------------------------------
template <int BN, int EPI, typename OutT>
__global__ __launch_bounds__(256) void gemm_tf32(
    const float* __restrict__ A, int lda, const float* __restrict__ W, int ldb,
    OutT* __restrict__ C, int ldc, const float* __restrict__ bias, int K)
{
    constexpr int BM = 128, BK = 16;
    constexpr int WN = BN / 4;
    constexpr int NI = WN / 8;
    constexpr int NITB = (BK * BN) / 1024;
    __shared__ uint2    As2[2][2][BM][4];
    __shared__ uint32_t Bs[2][BK][BN + 8];
    const int row0 = blockIdx.y * BM, col0 = blockIdx.x * BN;
    const int t = threadIdx.x, lane = t & 31, warp = t >> 5;
    const int wm = (warp & 1) * 64;
    const int wn = (warp >> 1) * WN;
    const int g = lane >> 2, c = lane & 3;
    const int am = t >> 1, aks = t & 1;

    float acc[4][NI][4];
    #pragma unroll
    for (int mi = 0; mi < 4; ++mi)
        #pragma unroll
        for (int ni = 0; ni < NI; ++ni)
            #pragma unroll
            for (int j = 0; j < 4; ++j) acc[mi][ni][j] = 0.f;

    float4 ra0, ra1, rb[NITB];

    auto gload = [&](int k0) {
        const float* ap = &A[(size_t)(row0 + am) * lda + k0 + aks * 8];
        ra0 = *(const float4*)(ap);
        ra1 = *(const float4*)(ap + 4);
        #pragma unroll
        for (int it = 0; it < NITB; ++it) {
            int kk = t / (BN / 4) + it * (1024 / BN);
            int nq = (t % (BN / 4)) * 4;
            rb[it] = *(const float4*)&W[(size_t)(k0 + kk) * ldb + col0 + nq];
        }
    };
    auto sstore = [&](int p) {
        As2[p][aks][am][0] = make_uint2(f2tf32(ra0.x), f2tf32(ra1.x));
        As2[p][aks][am][1] = make_uint2(f2tf32(ra0.y), f2tf32(ra1.y));
        As2[p][aks][am][2] = make_uint2(f2tf32(ra0.z), f2tf32(ra1.z));
        As2[p][aks][am][3] = make_uint2(f2tf32(ra0.w), f2tf32(ra1.w));
        #pragma unroll
        for (int it = 0; it < NITB; ++it) {
            int kk = t / (BN / 4) + it * (1024 / BN);
            int nq = (t % (BN / 4)) * 4;
            uint32_t* dst = &Bs[p][kk][nq];
            dst[0] = f2tf32(rb[it].x); dst[1] = f2tf32(rb[it].y);
            dst[2] = f2tf32(rb[it].z); dst[3] = f2tf32(rb[it].w);
        }
    };
    auto scompute = [&](int p) {
        #pragma unroll
        for (int ks = 0; ks < 2; ++ks) {
            const int kb = ks * 8;
            uint32_t af[4][4];
            #pragma unroll
            for (int mi = 0; mi < 4; ++mi) {
                int m = wm + mi * 16;
                uint2 u0 = As2[p][ks][m + g][c];
                uint2 u1 = As2[p][ks][m + g + 8][c];
                af[mi][0] = u0.x; af[mi][1] = u1.x;
                af[mi][2] = u0.y; af[mi][3] = u1.y;
            }
            uint32_t bf[NI][2];
            #pragma unroll
            for (int ni = 0; ni < NI; ++ni) {
                int n = wn + ni * 8 + g;
                bf[ni][0] = Bs[p][kb + c][n];
                bf[ni][1] = Bs[p][kb + c + 4][n];
            }
            #pragma unroll
            for (int mi = 0; mi < 4; ++mi)
                #pragma unroll
                for (int ni = 0; ni < NI; ++ni)
                    mma_tf32(acc[mi][ni], af[mi], bf[ni]);
        }
    };

    gload(0);
    sstore(0);
    __syncthreads();
    int p = 0;
    for (int k0 = 0; k0 < K; k0 += BK) {
        const bool more = (k0 + BK < K);
        if (more) gload(k0 + BK);
        scompute(p);
        if (more) sstore(p ^ 1);
        __syncthreads();
        p ^= 1;
    }
    #pragma unroll
    for (int mi = 0; mi < 4; ++mi) {
        #pragma unroll
        for (int ni = 0; ni < NI; ++ni) {
            int row = row0 + wm + mi * 16 + g;
            int col = col0 + wn + ni * 8 + 2 * c;
            #pragma unroll
            for (int half = 0; half < 2; ++half) {
                int r = row + half * 8;
                float v0 = acc[mi][ni][2 * half + 0];
                float v1 = acc[mi][ni][2 * half + 1];
                if (EPI >= 1) { v0 += bias[col]; v1 += bias[col + 1]; }
                if (EPI == 2) { v0 = fmaxf(v0, 0.f); v1 = fmaxf(v1, 0.f); }
                size_t off = (size_t)r * ldc + col;
                if (EPI == 3) { C[off] += v0; C[off + 1] += v1; }
                else          store2(v0, v1, &C[off]);
            }
        }
    }
}

__global__ void pack_w1cb(const float* __restrict__ m1, const float* __restrict__ r1,
                          __nv_bfloat16* __restrict__ w) {
    int i = blockIdx.x * 256 + threadIdx.x;
    if (i >= 1024 * 128) return;
    int n = i >> 7, k = i & 127;
    float v;
    if (n < 256)      v = m1[k * 256 + n];
    else if (n < 512) v = m1[(128 + k) * 256 + (n - 256)];
    else if (n < 768) v = r1[k * 256 + (n - 512)];
    else              v = r1[(128 + k) * 256 + (n - 768)];
    w[i] = __float2bfloat16(v);
}
__global__ void pack_w2cat(const float* __restrict__ m2, const float* __restrict__ r2,
                           float* __restrict__ w) {
    int i = blockIdx.x * 256 + threadIdx.x;
    if (i >= 512 * 128) return;
    int k = i >> 7, j = i & 127;
    w[i] = (k < 256) ? m2[k * 128 + j] : r2[(k - 256) * 128 + j];
}
__global__ void pack_u1bot(const float* __restrict__ u1, float* __restrict__ W1u) {
    int i = blockIdx.x * 256 + threadIdx.x;
    if (i >= 128 * 256) return;
    W1u[512 * 256 + i] = u1[128 * 256 + i];
}
__global__ void vmvr_kernel(const float* __restrict__ u1, const float* __restrict__ mb2,
                            const float* __restrict__ rb2, float* __restrict__ vm,
                            float* __restrict__ vr) {
    int j = threadIdx.x;
    float sm = 0.f, sr = 0.f;
    for (int k = 0; k < 128; ++k) {
        float u = u1[k * 256 + j];
        sm += mb2[k] * u;
        sr += rb2[k] * u;
    }
    vm[j] = sm; vr[j] = sr;
}
__global__ void pack_wecat(const float* __restrict__ m1, const float* __restrict__ r1,
                           const float* __restrict__ mb1, const float* __restrict__ rb1,
                           float* __restrict__ w, float* __restrict__ bcat) {
    int i = blockIdx.x * 256 + threadIdx.x;
    if (i < 64 * 512) {
        int k = i >> 9, j = i & 511;
        w[i] = (j < 256) ? m1[(256 + k) * 256 + j] : r1[(256 + k) * 256 + (j - 256)];
    }
    if (i < 512) bcat[i] = (i < 256) ? mb1[i] : rb1[i - 256];
}

__global__ void deg_count(const int* __restrict__ fr, const int* __restrict__ to,
                          int* din, int* dout, int E) {
    int e = blockIdx.x * 256 + threadIdx.x;
    if (e < E) { atomicAdd(&din[to[e]], 1); atomicAdd(&dout[fr[e]], 1); }
}
__global__ void exscan_kernel(const int* __restrict__ in, int* __restrict__ out, int n) {
    __shared__ int buf[1024];
    __shared__ int carry_s;
    int t = threadIdx.x;
    if (t == 0) carry_s = 0;
    __syncthreads();
    for (int base = 0; base < n; base += 1024) {
        int i = base + t;
        int v = (i < n) ? in[i] : 0;
        buf[t] = v;
        __syncthreads();
        for (int d = 1; d < 1024; d <<= 1) {
            int x = (t >= d) ? buf[t - d] : 0;
            __syncthreads();
            buf[t] += x;
            __syncthreads();
        }
        if (i < n) out[i] = carry_s + buf[t] - v;
        int tot = buf[1023];
        __syncthreads();
        if (t == 0) carry_s += tot;
        __syncthreads();
    }
    if (t == 0) out[n] = carry_s;
}
__global__ void csr_fill(const int* __restrict__ fr, const int* __restrict__ to,
                         int* cin, int* cout, int* iin, int* iout, int E) {
    int e = blockIdx.x * 256 + threadIdx.x;
    if (e < E) {
        int s  = atomicAdd(&cin [to[e]], 1); iin [s]  = e;
        int s2 = atomicAdd(&cout[fr[e]], 1); iout[s2] = e;
    }
}

__global__ __launch_bounds__(256) void permute_eenc(
    const float* __restrict__ eenc, const int* __restrict__ idx,
    const int* __restrict__ endp, float* __restrict__ out,
    int* __restrict__ ocsr, int E)
{
    int j = blockIdx.x * 8 + (threadIdx.x >> 5);
    if (j >= E) return;
    int lane = threadIdx.x & 31;
    int e = idx[j];
    if (lane == 0) ocsr[j] = endp[e];
    const float2* s2 = (const float2*)(eenc + (size_t)e * 64);
    float2* d2 = (float2*)(out + (size_t)j * 64);
    d2[lane] = s2[lane];
}

__global__ __launch_bounds__(256) void agg_kernel(
    const int* __restrict__ ptr, const int* __restrict__ ocsr,
    const __nv_bfloat162* __restrict__ AB, int aoff, int boff,
    const __nv_bfloat162* __restrict__ ecsr,
    float* __restrict__ catA, int ooff, int Nn)
{
    int n = (blockIdx.x * blockDim.x + threadIdx.x) >> 5;
    int lane = threadIdx.x & 31;
    if (n >= Nn) return;
    float bv[8], acc[8];
    const __nv_bfloat162* bp = AB + (size_t)n * 512 + boff;
    #pragma unroll
    for (int k = 0; k < 4; ++k) {
        float2 b2 = __bfloat1622float2(bp[lane + 32 * k]);
        bv[2 * k] = b2.x; bv[2 * k + 1] = b2.y;
        acc[2 * k] = 0.f; acc[2 * k + 1] = 0.f;
    }
    int s = ptr[n], e1 = ptr[n + 1];
    for (int j = s; j < e1; ++j) {
        int o = ocsr[j];
        const __nv_bfloat162* ap = AB + (size_t)o * 512 + aoff;
        const __nv_bfloat162* ep = ecsr + (size_t)j * 128;
        #pragma unroll
        for (int k = 0; k < 4; ++k) {
            float2 a2 = __bfloat1622float2(ap[lane + 32 * k]);
            float2 e2 = __bfloat1622float2(ep[lane + 32 * k]);
            acc[2 * k]     += fmaxf(a2.x + e2.x + bv[2 * k],     0.f);
            acc[2 * k + 1] += fmaxf(a2.y + e2.y + bv[2 * k + 1], 0.f);
        }
    }
    float2* op = (float2*)(catA + (size_t)n * 640 + ooff);
    #pragma unroll
    for (int k = 0; k < 4; ++k) op[lane + 32 * k] = make_float2(acc[2 * k], acc[2 * k + 1]);
}

__global__ void copy_h_kernel(const float* __restrict__ h, float* __restrict__ catA) {
    int n = blockIdx.x, t = threadIdx.x;
    catA[(size_t)n * 640 + 512 + t] = h[(size_t)n * 128 + t];
}

__global__ void build_sizes(const int* __restrict__ qs, const int* __restrict__ cs,
                            int* __restrict__ sizes, int B2) {
    int i = blockIdx.x * 256 + threadIdx.x;
    if (i < B2) sizes[i] = (i & 1) ? cs[i >> 1] : qs[i >> 1];
}
__global__ void scatter_kernel(const float* __restrict__ h, const int* __restrict__ gidx,
                               const int* __restrict__ starts, float* __restrict__ st) {
    int n = blockIdx.x, t = threadIdx.x;
    int g = gidx[n];
    int pos = n - starts[g];
    st[((size_t)g * 128 + pos) * 128 + t] = h[(size_t)n * 128 + t];
}
__global__ void mask_kernel(float* __restrict__ tt, const int* __restrict__ qs,
                            const int* __restrict__ cs) {
    int r = blockIdx.x, j = threadIdx.x;
    int b = r >> 8, side = (r >> 7) & 1, pos = r & 127;
    int sz = side ? cs[b] : qs[b];
    if (pos >= sz) tt[(size_t)r * 128 + j] = 0.f;
}

__global__ __launch_bounds__(256) void pair_gemm_kernel(const float* __restrict__ tt,
                                                        float* __restrict__ la) {
    int b = blockIdx.x;
    const float* Aq = tt + (size_t)(2 * b)     * 16384;
    const float* Ac = tt + (size_t)(2 * b + 1) * 16384;
    __shared__ float As[16][132], Bs[16][132];
    int t = threadIdx.x, tx = t & 15, ty = t >> 4;
    float acc[8][8];
    #pragma unroll
    for (int i = 0; i < 8; ++i)
        #pragma unroll
        for (int j = 0; j < 8; ++j) acc[i][j] = 0.f;
    for (int k0 = 0; k0 < 128; k0 += 16) {
        #pragma unroll
        for (int it = 0; it < 2; ++it) {
            int m = (t >> 2) + it * 64, kq = (t & 3) * 4;
            float4 v = *(const float4*)&Aq[m * 128 + k0 + kq];
            As[kq][m] = v.x; As[kq + 1][m] = v.y; As[kq + 2][m] = v.z; As[kq + 3][m] = v.w;
            float4 w = *(const float4*)&Ac[m * 128 + k0 + kq];
            Bs[kq][m] = w.x; Bs[kq + 1][m] = w.y; Bs[kq + 2][m] = w.z; Bs[kq + 3][m] = w.w;
        }
        __syncthreads();
        #pragma unroll
        for (int k = 0; k < 16; ++k) {
            float a[8], bv[8];
            *(float4*)(a)      = *(const float4*)&As[k][ty * 8];
            *(float4*)(a + 4)  = *(const float4*)&As[k][ty * 8 + 4];
            *(float4*)(bv)     = *(const float4*)&Bs[k][tx * 8];
            *(float4*)(bv + 4) = *(const float4*)&Bs[k][tx * 8 + 4];
            #pragma unroll
            for (int i = 0; i < 8; ++i)
                #pragma unroll
                for (int j = 0; j < 8; ++j) acc[i][j] += a[i] * bv[j];
        }
        __syncthreads();
    }
    float* dst = la + (size_t)b * 16384;
    #pragma unroll
    for (int i = 0; i < 8; ++i)
        #pragma unroll
        for (int j = 0; j < 8; ++j)
            dst[(ty * 8 + i) * 128 + tx * 8 + j] = acc[i][j] * 10.0f;
}

// ---------------------------------------------------------------------------
// Sinkhorn, dup-class compressed, all-log-domain (exact; exp-domain is
// unsound: underflowed entries/rows cannot be revived by renormalization).
// ---------------------------------------------------------------------------
__global__ __launch_bounds__(256) void sinkhorn_kernel(float* __restrict__ la_g,
                                                       const int* __restrict__ qs,
                                                       const int* __restrict__ cs) {
    extern __shared__ float P[];
    const int b = blockIdx.x;
    const int R = qs[b], C = cs[b];
    const float wR = (float)(128 - R), wC = (float)(128 - C);
    const int RT = (R < 128) ? R + 1 : 128;
    const int CT = (C < 128) ? C + 1 : 128;
    float* src = la_g + (size_t)b * 16384;
    const int t = threadIdx.x;
    for (int i = t; i < RT * CT; i += 256) {
        int q = i / CT, c = i % CT;
        P[q * 131 + c] = (q < R && c < C) ? src[q * 128 + c] : 0.f;
    }
    __syncthreads();
    const int warp = t >> 5, lane = t & 31;
    for (int iter = 0; iter < 20; ++iter) {
        for (int q = warp; q < RT; q += 8) {
            float m = -1e30f;
            for (int c = lane; c < CT; c += 32) m = fmaxf(m, P[q * 131 + c]);
            m = warp_max(m);
            float s = 0.f;
            for (int c = lane; c < CT; c += 32) {
                float w = (c == C) ? wC : 1.f;
                s += w * __expf(P[q * 131 + c] - m);
            }
            s = warp_sum(s);
            float lse = m + __logf(s);
            for (int c = lane; c < CT; c += 32) P[q * 131 + c] -= lse;
        }
        __syncthreads();
        for (int c = warp; c < CT; c += 8) {
            float m = -1e30f;
            for (int q = lane; q < RT; q += 32) m = fmaxf(m, P[q * 131 + c]);
            m = warp_max(m);
            float s = 0.f;
            for (int q = lane; q < RT; q += 32) {
                float w = (q == R) ? wR : 1.f;
                s += w * __expf(P[q * 131 + c] - m);
            }
            s = warp_sum(s);
            float lse = m + __logf(s);
            for (int q = lane; q < RT; q += 32) P[q * 131 + c] -= lse;
        }
        __syncthreads();
    }
    for (int i = t; i < 16384; i += 256) {
        int q = i >> 7, c = i & 127;
        int qe = (q < R) ? q : R;
        int ce = (c < C) ? c : C;
        src[i] = __expf(P[qe * 131 + ce]);
    }
}

__global__ __launch_bounds__(256) void score_kernel(const float* __restrict__ plan,
                                                    const float* __restrict__ stacked,
                                                    float* __restrict__ out) {
    int b = blockIdx.x;
    const float* P  = plan    + (size_t)b * 16384;
    const float* Q  = stacked + (size_t)(2 * b)     * 16384;
    const float* Cm = stacked + (size_t)(2 * b + 1) * 16384;
    __shared__ float As[16][132], Bs[16][132];
    int t = threadIdx.x, tx = t & 15, ty = t >> 4;
    float acc[8][8];
    #pragma unroll
    for (int i = 0; i < 8; ++i)
        #pragma unroll
        for (int j = 0; j < 8; ++j) acc[i][j] = 0.f;
    for (int k0 = 0; k0 < 128; k0 += 16) {
        #pragma unroll
        for (int it = 0; it < 2; ++it) {
            int m = (t >> 2) + it * 64, kq = (t & 3) * 4;
            float4 v = *(const float4*)&P[m * 128 + k0 + kq];
            As[kq][m] = v.x; As[kq + 1][m] = v.y; As[kq + 2][m] = v.z; As[kq + 3][m] = v.w;
        }
        #pragma unroll
        for (int it = 0; it < 2; ++it) {
            int kk = (t >> 5) + it * 8, nq = (t & 31) * 4;
            *(float4*)&Bs[kk][nq] = *(const float4*)&Cm[(k0 + kk) * 128 + nq];
        }
        __syncthreads();
        #pragma unroll
        for (int k = 0; k < 16; ++k) {
            float a[8], bv[8];
            *(float4*)(a)      = *(const float4*)&As[k][ty * 8];
            *(float4*)(a + 4)  = *(const float4*)&As[k][ty * 8 + 4];
            *(float4*)(bv)     = *(const float4*)&Bs[k][tx * 8];
            *(float4*)(bv + 4) = *(const float4*)&Bs[k][tx * 8 + 4];
            #pragma unroll
            for (int i = 0; i < 8; ++i)
                #pragma unroll
                for (int j = 0; j < 8; ++j) acc[i][j] += a[i] * bv[j];
        }
        __syncthreads();
    }
    float s = 0.f;
    #pragma unroll
    for (int i = 0; i < 8; ++i)
        #pragma unroll
        for (int j = 0; j < 8; ++j)
            s += fmaxf(Q[(ty * 8 + i) * 128 + tx * 8 + j] - acc[i][j], 0.f);
    s = warp_sum(s);
    __shared__ float red[8];
    if ((t & 31) == 0) red[t >> 5] = s;
    __syncthreads();
    if (t == 0) {
        float tot = 0.f;
        #pragma unroll
        for (int i = 0; i < 8; ++i) tot += red[i];
        out[b] = -tot;
    }
}

template <typename T>
static T* sym(const void* s) { void* p = nullptr; cudaGetSymbolAddress(&p, s); return (T*)p; }

extern "C" void kernel_launch(void* const* d_in, const int* in_sizes, int n_in,
                              void* d_out, int out_size) {
    const float* nf  = (const float*)d_in[0];
    const float* ef  = (const float*)d_in[1];
    const float* enW = (const float*)d_in[2];  const float* enB = (const float*)d_in[3];
    const float* eeW = (const float*)d_in[4];  const float* eeB = (const float*)d_in[5];
    const float* m1  = (const float*)d_in[6];  const float* mb1 = (const float*)d_in[7];
    const float* m2  = (const float*)d_in[8];  const float* mb2 = (const float*)d_in[9];
    const float* r1  = (const float*)d_in[10]; const float* rb1 = (const float*)d_in[11];
    const float* r2  = (const float*)d_in[12]; const float* rb2 = (const float*)d_in[13];
    const float* u1  = (const float*)d_in[14]; const float* ub1 = (const float*)d_in[15];
    const float* u2  = (const float*)d_in[16]; const float* ub2 = (const float*)d_in[17];
    const float* f1  = (const float*)d_in[18]; const float* f1b = (const float*)d_in[19];
    const float* f2  = (const float*)d_in[20]; const float* f2b = (const float*)d_in[21];
    const int* fr  = (const int*)d_in[22];
    const int* to  = (const int*)d_in[23];
    const int* gix = (const int*)d_in[24];
    const int* qs  = (const int*)d_in[25];
    const int* cs  = (const int*)d_in[26];
    const int E  = in_sizes[22];
    const int N  = in_sizes[24];
    const int B  = in_sizes[25];
    const int B2 = 2 * B;
    float* out = (float*)d_out;

    float* h    = sym<float>(g_h);    float* eenc = sym<float>(g_eenc);
    float* eP   = sym<float>(g_eP);
    __nv_bfloat16* ABh = sym<__nv_bfloat16>(g_ABh);
    __nv_bfloat16* eMc = sym<__nv_bfloat16>(g_eMc);
    __nv_bfloat16* eRc = sym<__nv_bfloat16>(g_eRc);
    __nv_bfloat16* W1cb = sym<__nv_bfloat16>(g_W1cb);
    float* catA = sym<float>(g_catA);
    float* hid  = sym<float>(g_hid);  float* tt   = sym<float>(g_t);
    float* stk  = sym<float>(g_stk);  float* la   = sym<float>(g_la);
    float* W2c  = sym<float>(g_W2cat);
    float* W1u  = sym<float>(g_W1u);
    float* vm   = sym<float>(g_vm);   float* vr   = sym<float>(g_vr);
    float* Wec  = sym<float>(g_Wecat); float* bec = sym<float>(g_becat);
    int* sizes = sym<int>(g_sizes); int* starts = sym<int>(g_starts);
    int* din = sym<int>(g_din);   int* dout = sym<int>(g_dout);
    int* pin = sym<int>(g_pin);   int* pout = sym<int>(g_pout);
    int* cin = sym<int>(g_cin);   int* cout = sym<int>(g_cout);
    int* iin = sym<int>(g_iin);   int* iout = sym<int>(g_iout);
    int* oin = sym<int>(g_oin);   int* oout = sym<int>(g_oout);
    float* ePa = eP;
    float* ePb = eP + (size_t)EMAX * 64;

    const int ABP_SMEM = 2 * 4096 * 8;  // 64 KB

    static bool attr_set = false;
    if (!attr_set) {
        cudaFuncSetAttribute(sinkhorn_kernel,
                             cudaFuncAttributeMaxDynamicSharedMemorySize, 129 * 131 * 4);
        cudaFuncSetAttribute(abp_fused,
                             cudaFuncAttributeMaxDynamicSharedMemorySize, ABP_SMEM);
        attr_set = true;
    }

    // ---- launches 1-6; #4 (= ncu capture) is abp_fused ----
    gemm_tf32<128, 1, float><<<dim3(1, N / 128), 256>>>(nf, 32, enW, 128, h, 128, enB, 32);
    pack_w1cb<<<(1024 * 128 + 255) / 256, 256>>>(m1, r1, W1cb);
    pack_wecat<<<(64 * 512 + 255) / 256, 256>>>(m1, r1, mb1, rb1, Wec, bec);
    abp_fused<<<N / 128, 256, ABP_SMEM>>>(h, W1cb, ABh);
    pack_w2cat<<<(512 * 128 + 255) / 256, 256>>>(m2, r2, W2c);
    gemm_tf32<64, 1, float><<<dim3(1, E / 128), 256>>>(ef, 16, eeW, 64, eenc, 64, eeB, 16);

    // ---- fused-update precompute: W1u = [W2c@u1_top ; u1_bot], vm, vr ----
    gemm_tf32<128, 0, float><<<dim3(2, 4), 256>>>(W2c, 128, u1, 256, W1u, 256, nullptr, 128);
    pack_u1bot<<<(128 * 256 + 255) / 256, 256>>>(u1, W1u);
    vmvr_kernel<<<1, 256>>>(u1, mb2, rb2, vm, vr);

    // ---- graph structure ----
    zero_i<<<(N + 255) / 256, 256>>>(din, N);
    zero_i<<<(N + 255) / 256, 256>>>(dout, N);
    build_sizes<<<(B2 + 255) / 256, 256>>>(qs, cs, sizes, B2);
    exscan_kernel<<<1, 1024>>>(sizes, starts, B2);
    deg_count<<<(E + 255) / 256, 256>>>(fr, to, din, dout, E);
    exscan_kernel<<<1, 1024>>>(din, pin, N);
    exscan_kernel<<<1, 1024>>>(dout, pout, N);
    copy_i<<<(N + 255) / 256, 256>>>(pin, cin, N);
    copy_i<<<(N + 255) / 256, 256>>>(pout, cout, N);
    csr_fill<<<(E + 255) / 256, 256>>>(fr, to, cin, cout, iin, iout, E);

    // ---- edge constants: permute eenc, bf16s GEMM directly to bf16 CSR ----
    permute_eenc<<<(E + 7) / 8, 256>>>(eenc, iin,  fr, ePa, oin,  E);
    permute_eenc<<<(E + 7) / 8, 256>>>(eenc, iout, to, ePb, oout, E);
    gemm_bf16s<1, __nv_bfloat16><<<dim3(2, E / 128), 256>>>(
        ePa, 64, Wec, 512, eMc, 256, bec, 64, nullptr, nullptr, nullptr, nullptr);
    gemm_bf16s<1, __nv_bfloat16><<<dim3(2, E / 128), 256>>>(
        ePb, 64, Wec + 256, 512, eRc, 256, bec + 256, 64, nullptr, nullptr, nullptr, nullptr);

    // ---- propagation rounds (round 0's ABp already done above) ----
    for (int r = 0; r < 5; ++r) {
        if (r > 0)
            abp_fused<<<N / 128, 256, ABP_SMEM>>>(h, W1cb, ABh);
        agg_kernel<<<(N + 7) / 8, 256>>>(pin,  oin,  (const __nv_bfloat162*)ABh, 0,   128,
                                         (const __nv_bfloat162*)eMc, catA, 0,   N);
        agg_kernel<<<(N + 7) / 8, 256>>>(pout, oout, (const __nv_bfloat162*)ABh, 256, 384,
                                         (const __nv_bfloat162*)eRc, catA, 256, N);
        copy_h_kernel<<<N, 128>>>(h, catA);
        gemm_bf16s<4, float><<<dim3(2, N / 128), 256>>>(
            catA, 640, W1u, 256, hid, 256, ub1, 640, pin, pout, vm, vr);
        gemm_bf16s<3, float><<<dim3(1, N / 128), 256>>>(
            hid, 256, u2, 128, h, 128, ub2, 256, nullptr, nullptr, nullptr, nullptr);
    }

    // ---- stack + transform ----
    zero_f<<<2048, 256>>>(stk, (size_t)B2 * 16384);
    scatter_kernel<<<N, 128>>>(h, gix, starts, stk);
    gemm_bf16s<2, float><<<dim3(1, B2), 256>>>(
        stk, 128, f1, 128, hid, 128, f1b, 128, nullptr, nullptr, nullptr, nullptr);
    gemm_tf32<128, 1, float><<<dim3(1, B2 * 128 / 128), 256>>>(hid, 128, f2, 128, tt, 128, f2b, 128);
    mask_kernel<<<B2 * 128, 128>>>(tt, qs, cs);

    // ---- sinkhorn + score ----
    pair_gemm_kernel<<<B, 256>>>(tt, la);
    sinkhorn_kernel<<<B, 256, 129 * 131 * 4>>>(la, qs, cs);
    score_kernel<<<B, 256>>>(la, stk, out);
}